// round 2
// baseline (speedup 1.0000x reference)
#include <cuda_runtime.h>
#include <math.h>

#define N_NODES 20000
#define N_EDGES 320000
#define ETOT    (N_EDGES + N_NODES)
#define FEAT    64
#define HID     128
#define KIN     (HID + FEAT)   /* 192 */
#define NEG     0.2f

/* ------------------ scratch (device globals: no allocation allowed) ------ */
__device__ float g_xin[N_NODES * KIN];
__device__ float g_x0 [N_NODES * HID];
__device__ float g_xl1[N_NODES * 4 * HID];
__device__ float g_xr1[N_NODES * 4 * HID];
__device__ float g_x1 [N_NODES * 4 * HID];
__device__ float g_xl2[N_NODES * HID];
__device__ float g_xr2[N_NODES * HID];
__device__ float g_x2 [N_NODES * HID];
__device__ int   g_deg[N_NODES];
__device__ int   g_off[N_NODES + 1];
__device__ int   g_cur[N_NODES];
__device__ int   g_srcs[ETOT];

/* ------------------ CSR build ------------------------------------------- */
__global__ void k_init_deg() {
    int i = blockIdx.x * blockDim.x + threadIdx.x;
    if (i < N_NODES) g_deg[i] = 1;            /* self loop */
}

__global__ void k_count(const int* __restrict__ ei) {
    int e = blockIdx.x * blockDim.x + threadIdx.x;
    if (e < N_EDGES) atomicAdd(&g_deg[ei[N_EDGES + e]], 1);
}

__global__ void k_scan() {
    __shared__ int ps[1024];
    int t = threadIdx.x;
    const int CH = (N_NODES + 1023) / 1024;   /* 20 */
    int base = t * CH;
    int s = 0;
    for (int i = 0; i < CH; i++) { int idx = base + i; if (idx < N_NODES) s += g_deg[idx]; }
    ps[t] = s;
    __syncthreads();
    for (int off = 1; off < 1024; off <<= 1) {
        int v = (t >= off) ? ps[t - off] : 0;
        __syncthreads();
        ps[t] += v;
        __syncthreads();
    }
    int run = ps[t] - s;
    for (int i = 0; i < CH; i++) {
        int idx = base + i;
        if (idx < N_NODES) { g_off[idx] = run; g_cur[idx] = run; run += g_deg[idx]; }
    }
    if (t == 1023) g_off[N_NODES] = ps[1023];
}

__global__ void k_scatter(const int* __restrict__ ei) {
    int e = blockIdx.x * blockDim.x + threadIdx.x;
    if (e < N_EDGES) {
        int d = ei[N_EDGES + e];
        int p = atomicAdd(&g_cur[d], 1);
        g_srcs[p] = ei[e];
    }
}

__global__ void k_selfloop() {
    int i = blockIdx.x * blockDim.x + threadIdx.x;
    if (i < N_NODES) {
        int p = atomicAdd(&g_cur[i], 1);
        g_srcs[p] = i;
    }
}

/* ------------------ input gather: [emb[id] ; feats] --------------------- */
__global__ void k_gather(const float* __restrict__ xp, const float* __restrict__ emb) {
    int idx = blockIdx.x * blockDim.x + threadIdx.x;
    if (idx >= N_NODES * KIN) return;
    int i = idx / KIN, k = idx - i * KIN;
    float v;
    if (k < HID) {
        int id = (int)xp[i * (FEAT + 1)];
        v = emb[id * HID + k];
    } else {
        v = xp[i * (FEAT + 1) + 1 + (k - HID)];
    }
    g_xin[idx] = v;
}

/* ------------------ fp32 SGEMM: C = act(A[M,K] @ B[K,N] + bias) ---------- */
/* BM=128 BN=128 BK=16, 256 threads, 8x8 register tile. K%16==0, N%128==0.  */
__global__ __launch_bounds__(256, 2)
void sgemm(const float* __restrict__ A, const float* __restrict__ B,
           const float* __restrict__ bias, float* __restrict__ C,
           int M, int N, int K, int relu)
{
    __shared__ float As[16][132];   /* padded, transposed */
    __shared__ float Bs[16][128];
    int tid = threadIdx.x;
    int tx = tid & 15, ty = tid >> 4;
    int row0 = blockIdx.y * 128, col0 = blockIdx.x * 128;

    float acc[8][8];
#pragma unroll
    for (int i = 0; i < 8; i++)
#pragma unroll
        for (int j = 0; j < 8; j++) acc[i][j] = 0.f;

    for (int k0 = 0; k0 < K; k0 += 16) {
#pragma unroll
        for (int q = 0; q < 2; q++) {           /* A tile: 128x16 */
            int idx = tid + 256 * q;
            int m = idx >> 2, kq = idx & 3;
            int row = row0 + m;
            float4 v = make_float4(0.f, 0.f, 0.f, 0.f);
            if (row < M) v = *(const float4*)(A + (size_t)row * K + (k0 + kq * 4));
            As[kq * 4 + 0][m] = v.x; As[kq * 4 + 1][m] = v.y;
            As[kq * 4 + 2][m] = v.z; As[kq * 4 + 3][m] = v.w;
        }
#pragma unroll
        for (int q = 0; q < 2; q++) {           /* B tile: 16x128 */
            int idx = tid + 256 * q;
            int kr = idx >> 5, nq = idx & 31;
            *(float4*)&Bs[kr][nq * 4] =
                *(const float4*)(B + (size_t)(k0 + kr) * N + col0 + nq * 4);
        }
        __syncthreads();
#pragma unroll
        for (int kk = 0; kk < 16; kk++) {
            float a[8], b[8];
            *(float4*)&a[0] = *(float4*)&As[kk][ty * 8];
            *(float4*)&a[4] = *(float4*)&As[kk][ty * 8 + 4];
            *(float4*)&b[0] = *(float4*)&Bs[kk][tx * 8];
            *(float4*)&b[4] = *(float4*)&Bs[kk][tx * 8 + 4];
#pragma unroll
            for (int i = 0; i < 8; i++)
#pragma unroll
                for (int j = 0; j < 8; j++) acc[i][j] += a[i] * b[j];
        }
        __syncthreads();
    }

#pragma unroll
    for (int i = 0; i < 8; i++) {
        int row = row0 + ty * 8 + i;
        if (row >= M) continue;
#pragma unroll
        for (int jq = 0; jq < 2; jq++) {
            int col = col0 + tx * 8 + jq * 4;
            float4 o = make_float4(acc[i][jq * 4 + 0], acc[i][jq * 4 + 1],
                                   acc[i][jq * 4 + 2], acc[i][jq * 4 + 3]);
            if (bias) { o.x += bias[col]; o.y += bias[col + 1]; o.z += bias[col + 2]; o.w += bias[col + 3]; }
            if (relu) { o.x = fmaxf(o.x, 0.f); o.y = fmaxf(o.y, 0.f); o.z = fmaxf(o.z, 0.f); o.w = fmaxf(o.w, 0.f); }
            *(float4*)(C + (size_t)row * N + col) = o;
        }
    }
}

/* ------------------ fused GATv2 softmax-aggregation --------------------- */
__device__ __forceinline__ float lrelu(float x) { return x > 0.f ? x : NEG * x; }

template <int HEADS>
__global__ void gat_agg(const float* __restrict__ xl, const float* __restrict__ xr,
                        const float* __restrict__ att, const float* __restrict__ bias,
                        float* __restrict__ out, int relu)
{
    int w = (blockIdx.x * blockDim.x + threadIdx.x) >> 5;     /* one warp per (dst,head) */
    int lane = threadIdx.x & 31;
    if (w >= N_NODES * HEADS) return;
    int dst = w / HEADS;
    int h   = w - dst * HEADS;
    const int D = HEADS * HID;
    int cb = h * HID + lane * 4;

    float4 a4 = *(const float4*)(att + h * HID + lane * 4);
    float4 r4 = *(const float4*)(xr + (size_t)dst * D + cb);

    float m = -1e30f, s = 0.f;
    float4 acc = make_float4(0.f, 0.f, 0.f, 0.f);

    int j = g_off[dst], end = g_off[dst + 1];
    for (; j < end; j++) {
        int src = g_srcs[j];
        float4 l4 = *(const float4*)(xl + (size_t)src * D + cb);
        float p = lrelu(l4.x + r4.x) * a4.x;
        p      += lrelu(l4.y + r4.y) * a4.y;
        p      += lrelu(l4.z + r4.z) * a4.z;
        p      += lrelu(l4.w + r4.w) * a4.w;
#pragma unroll
        for (int o = 16; o > 0; o >>= 1) p += __shfl_xor_sync(0xffffffffu, p, o);
        /* online softmax */
        float mn = fmaxf(m, p);
        float c  = __expf(m - mn);
        float wg = __expf(p - mn);
        s = s * c + wg;
        acc.x = acc.x * c + wg * l4.x;
        acc.y = acc.y * c + wg * l4.y;
        acc.z = acc.z * c + wg * l4.z;
        acc.w = acc.w * c + wg * l4.w;
        m = mn;
    }
    float inv = 1.f / (s + 1e-16f);
    float4 bb = *(const float4*)(bias + h * HID + lane * 4);
    float4 o4;
    o4.x = acc.x * inv + bb.x;
    o4.y = acc.y * inv + bb.y;
    o4.z = acc.z * inv + bb.z;
    o4.w = acc.w * inv + bb.w;
    if (relu) {
        o4.x = fmaxf(o4.x, 0.f); o4.y = fmaxf(o4.y, 0.f);
        o4.z = fmaxf(o4.z, 0.f); o4.w = fmaxf(o4.w, 0.f);
    }
    *(float4*)(out + (size_t)dst * D + cb) = o4;
}

/* ------------------ final [N,128] @ [128,10] + b ------------------------ */
__global__ void k_out(const float* __restrict__ x2, const float* __restrict__ W,
                      const float* __restrict__ b, float* __restrict__ y)
{
    __shared__ float Ws[HID * 10];
    __shared__ float bs[10];
    for (int i = threadIdx.x; i < HID * 10; i += blockDim.x) Ws[i] = W[i];
    if (threadIdx.x < 10) bs[threadIdx.x] = b[threadIdx.x];
    __syncthreads();
    int w = (blockIdx.x * blockDim.x + threadIdx.x) >> 5;     /* warp per row */
    int lane = threadIdx.x & 31;
    if (w >= N_NODES) return;
    float4 v = *(const float4*)(x2 + (size_t)w * HID + lane * 4);
    int k = lane * 4;
    float p[10];
#pragma unroll
    for (int o = 0; o < 10; o++)
        p[o] = v.x * Ws[(k + 0) * 10 + o] + v.y * Ws[(k + 1) * 10 + o] +
               v.z * Ws[(k + 2) * 10 + o] + v.w * Ws[(k + 3) * 10 + o];
#pragma unroll
    for (int o = 0; o < 10; o++)
#pragma unroll
        for (int off = 16; off > 0; off >>= 1)
            p[o] += __shfl_xor_sync(0xffffffffu, p[o], off);
    if (lane < 10) y[(size_t)w * 10 + lane] = p[lane] + bs[lane];
}

/* ------------------ launch ---------------------------------------------- */
extern "C" void kernel_launch(void* const* d_in, const int* in_sizes, int n_in,
                              void* d_out, int out_size)
{
    const float* x_player   = (const float*)d_in[0];
    const int*   edge_index = (const int*)  d_in[1];
    const float* emb        = (const float*)d_in[2];
    const float* proj_W     = (const float*)d_in[3];
    const float* proj_b     = (const float*)d_in[4];
    const float* W1l        = (const float*)d_in[5];
    const float* W1r        = (const float*)d_in[6];
    const float* att1       = (const float*)d_in[7];
    const float* b1         = (const float*)d_in[8];
    const float* W2l        = (const float*)d_in[9];
    const float* W2r        = (const float*)d_in[10];
    const float* att2       = (const float*)d_in[11];
    const float* b2         = (const float*)d_in[12];
    const float* out_W      = (const float*)d_in[13];
    const float* out_b      = (const float*)d_in[14];
    float* y = (float*)d_out;

    float *xin, *x0, *xl1, *xr1, *x1, *xl2, *xr2, *x2;
    cudaGetSymbolAddress((void**)&xin, g_xin);
    cudaGetSymbolAddress((void**)&x0,  g_x0);
    cudaGetSymbolAddress((void**)&xl1, g_xl1);
    cudaGetSymbolAddress((void**)&xr1, g_xr1);
    cudaGetSymbolAddress((void**)&x1,  g_x1);
    cudaGetSymbolAddress((void**)&xl2, g_xl2);
    cudaGetSymbolAddress((void**)&xr2, g_xr2);
    cudaGetSymbolAddress((void**)&x2,  g_x2);

    /* CSR build */
    k_init_deg<<<(N_NODES + 255) / 256, 256>>>();
    k_count   <<<(N_EDGES + 255) / 256, 256>>>(edge_index);
    k_scan    <<<1, 1024>>>();
    k_scatter <<<(N_EDGES + 255) / 256, 256>>>(edge_index);
    k_selfloop<<<(N_NODES + 255) / 256, 256>>>();

    /* embed gather + proj */
    k_gather<<<(N_NODES * KIN + 255) / 256, 256>>>(x_player, emb);
    sgemm<<<dim3(1, 157), 256>>>(xin, proj_W, proj_b, x0, N_NODES, HID, KIN, 1);

    /* GAT layer 1 (heads=4) */
    sgemm<<<dim3(4, 157), 256>>>(x0, W1l, nullptr, xl1, N_NODES, 4 * HID, HID, 0);
    sgemm<<<dim3(4, 157), 256>>>(x0, W1r, nullptr, xr1, N_NODES, 4 * HID, HID, 0);
    gat_agg<4><<<(N_NODES * 4 * 32 + 255) / 256, 256>>>(xl1, xr1, att1, b1, x1, 1);

    /* GAT layer 2 (heads=1) */
    sgemm<<<dim3(1, 157), 256>>>(x1, W2l, nullptr, xl2, N_NODES, HID, 4 * HID, 0);
    sgemm<<<dim3(1, 157), 256>>>(x1, W2r, nullptr, xr2, N_NODES, HID, 4 * HID, 0);
    gat_agg<1><<<(N_NODES * 32 + 255) / 256, 256>>>(xl2, xr2, att2, b2, x2, 0);

    /* output projection */
    k_out<<<(N_NODES * 32 + 255) / 256, 256>>>(x2, out_W, out_b, y);
}

// round 5
// speedup vs baseline: 1.5657x; 1.5657x over previous
#include <cuda_runtime.h>
#include <cuda_bf16.h>
#include <stdint.h>
#include <math.h>

#define N_NODES 20000
#define MPAD    20096          /* 157 * 128 */
#define N_EDGES 320000
#define ETOT    (N_EDGES + N_NODES)
#define FEAT    64
#define HID     128
#define KIN     (HID + FEAT)   /* 192 */
#define NEG     0.2f

typedef __nv_bfloat16 bf16;

/* ------------------ scratch (device globals: no allocation allowed) ------ */
/* pad rows [N_NODES, MPAD) are never written -> stay zero                   */
__device__ __align__(256) bf16  g_xinh[MPAD * KIN];
__device__ __align__(256) bf16  g_xinl[MPAD * KIN];
__device__ __align__(256) bf16  g_x0h [MPAD * HID];
__device__ __align__(256) bf16  g_x0l [MPAD * HID];
__device__ __align__(256) float g_xl1 [MPAD * 4 * HID];
__device__ __align__(256) float g_xr1 [MPAD * 4 * HID];
__device__ __align__(256) bf16  g_x1h [MPAD * 4 * HID];
__device__ __align__(256) bf16  g_x1l [MPAD * 4 * HID];
__device__ __align__(256) float g_xl2 [MPAD * HID];
__device__ __align__(256) float g_xr2 [MPAD * HID];
__device__ __align__(256) float g_x2  [MPAD * HID];
/* transposed split weights: [N,K] K-major */
__device__ __align__(256) bf16  g_pWh [HID * KIN],      g_pWl [HID * KIN];
__device__ __align__(256) bf16  g_W1lh[4 * HID * HID],  g_W1ll[4 * HID * HID];
__device__ __align__(256) bf16  g_W1rh[4 * HID * HID],  g_W1rl[4 * HID * HID];
__device__ __align__(256) bf16  g_W2lh[HID * 4 * HID],  g_W2ll[HID * 4 * HID];
__device__ __align__(256) bf16  g_W2rh[HID * 4 * HID],  g_W2rl[HID * 4 * HID];
__device__ int   g_deg[N_NODES];
__device__ int   g_off[N_NODES + 1];
__device__ int   g_cur[N_NODES];
__device__ int   g_srcs[ETOT];

/* ------------------ pack helpers ---------------------------------------- */
__device__ __forceinline__ unsigned int pack2(float a, float b) {
    union { __nv_bfloat162 v; unsigned int u; } c;
    c.v = __nv_bfloat162(__float2bfloat16(a), __float2bfloat16(b));
    return c.u;
}
__device__ __forceinline__ void split_store4(bf16* hp, bf16* lp, size_t o, float4 v) {
    bf16 hx = __float2bfloat16(v.x), hy = __float2bfloat16(v.y);
    bf16 hz = __float2bfloat16(v.z), hw = __float2bfloat16(v.w);
    union { __nv_bfloat162 v; unsigned int u; } a, b;
    a.v = __nv_bfloat162(hx, hy); b.v = __nv_bfloat162(hz, hw);
    *(uint2*)(hp + o) = make_uint2(a.u, b.u);
    *(uint2*)(lp + o) = make_uint2(
        pack2(v.x - __bfloat162float(hx), v.y - __bfloat162float(hy)),
        pack2(v.z - __bfloat162float(hz), v.w - __bfloat162float(hw)));
}

/* ------------------ PTX helpers (all baseline sm_80+, no 'a' features) -- */
__device__ __forceinline__ unsigned int smem_u32(const void* p) {
    unsigned int a;
    asm("{ .reg .u64 t; cvta.to.shared.u64 t, %1; cvt.u32.u64 %0, t; }" : "=r"(a) : "l"(p));
    return a;
}
#define CP16(dst, src)  asm volatile("cp.async.ca.shared.global [%0], [%1], 16;" :: "r"(dst), "l"(src) : "memory")
#define CP_COMMIT()     asm volatile("cp.async.commit_group;" ::: "memory")
#define CP_WAIT1()      asm volatile("cp.async.wait_group 1;" ::: "memory")
#define CP_WAIT0()      asm volatile("cp.async.wait_group 0;" ::: "memory")

#define LDSM4(d, addr) \
    asm volatile("ldmatrix.sync.aligned.m8n8.x4.shared.b16 {%0,%1,%2,%3}, [%4];" \
        : "=r"((d)[0]), "=r"((d)[1]), "=r"((d)[2]), "=r"((d)[3]) : "r"(addr))

#define MMA16816(c, a, b) \
    asm volatile("mma.sync.aligned.m16n8k16.row.col.f32.bf16.bf16.f32 " \
        "{%0,%1,%2,%3}, {%4,%5,%6,%7}, {%8,%9}, {%0,%1,%2,%3};" \
        : "+f"((c)[0]), "+f"((c)[1]), "+f"((c)[2]), "+f"((c)[3]) \
        : "r"((a)[0]), "r"((a)[1]), "r"((a)[2]), "r"((a)[3]), \
          "r"((b)[0]), "r"((b)[1]))

/* ------------------ CSR build ------------------------------------------- */
__global__ void k_init_deg() {
    int i = blockIdx.x * blockDim.x + threadIdx.x;
    if (i < N_NODES) g_deg[i] = 1;
}
__global__ void k_count(const int* __restrict__ ei) {
    int e = blockIdx.x * blockDim.x + threadIdx.x;
    if (e < N_EDGES) atomicAdd(&g_deg[ei[N_EDGES + e]], 1);
}
__global__ void k_scan() {
    __shared__ int ps[1024];
    int t = threadIdx.x;
    const int CH = (N_NODES + 1023) / 1024;
    int base = t * CH, s = 0;
    for (int i = 0; i < CH; i++) { int idx = base + i; if (idx < N_NODES) s += g_deg[idx]; }
    ps[t] = s;
    __syncthreads();
    for (int off = 1; off < 1024; off <<= 1) {
        int v = (t >= off) ? ps[t - off] : 0;
        __syncthreads();
        ps[t] += v;
        __syncthreads();
    }
    int run = ps[t] - s;
    for (int i = 0; i < CH; i++) {
        int idx = base + i;
        if (idx < N_NODES) { g_off[idx] = run; g_cur[idx] = run; run += g_deg[idx]; }
    }
    if (t == 1023) g_off[N_NODES] = ps[1023];
}
__global__ void k_scatter(const int* __restrict__ ei) {
    int e = blockIdx.x * blockDim.x + threadIdx.x;
    if (e < N_EDGES) {
        int d = ei[N_EDGES + e];
        int p = atomicAdd(&g_cur[d], 1);
        g_srcs[p] = ei[e];
    }
}
__global__ void k_selfloop() {
    int i = blockIdx.x * blockDim.x + threadIdx.x;
    if (i < N_NODES) {
        int p = atomicAdd(&g_cur[i], 1);
        g_srcs[p] = i;
    }
}

/* ------------------ input gather -> split bf16 --------------------------- */
__device__ __forceinline__ void split_store(bf16* h, bf16* l, size_t idx, float v) {
    bf16 hb = __float2bfloat16(v);
    h[idx] = hb;
    l[idx] = __float2bfloat16(v - __bfloat162float(hb));
}

__global__ void k_gather(const float* __restrict__ xp, const float* __restrict__ emb) {
    int idx = blockIdx.x * blockDim.x + threadIdx.x;
    if (idx >= N_NODES * KIN) return;
    int i = idx / KIN, k = idx - i * KIN;
    float v;
    if (k < HID) {
        int id = (int)xp[i * (FEAT + 1)];
        v = emb[id * HID + k];
    } else {
        v = xp[i * (FEAT + 1) + 1 + (k - HID)];
    }
    split_store(g_xinh, g_xinl, (size_t)i * KIN + k, v);
}

/* ------------------ weight transpose + split: [K,N] -> [N,K] ------------- */
__global__ void k_convw(const float* __restrict__ W, bf16* __restrict__ h,
                        bf16* __restrict__ l, int K, int N) {
    int idx = blockIdx.x * blockDim.x + threadIdx.x;
    if (idx >= K * N) return;
    int k = idx / N, n = idx - k * N;
    split_store(h, l, (size_t)n * K + k, W[(size_t)k * N + n]);
}

/* ------------------ HMMA split-bf16 GEMM --------------------------------- */
/* C[M=MPAD, Ntot] = A[M,Ktot] @ B^T (B stored [Ntot,Ktot] K-major)          */
/* CTA 128x128, BK=32, 8 warps (4M x 2N), warp tile 32x64.                   */
/* D += Ah*Bh + Ah*Bl + Al*Bh  via mma.sync m16n8k16 bf16.                   */
#define PADK   40                       /* bf16 elems per smem row */
#define TILE_EL (128 * PADK)            /* 5120 */
#define STG_EL  (4 * TILE_EL)           /* 20480 per stage */
#define SM_SZ   (2 * STG_EL * 2)        /* 81920 bytes */

__device__ __forceinline__ void stage_load(
    unsigned sbase, int s,
    const bf16* __restrict__ Ah, const bf16* __restrict__ Al,
    const bf16* __restrict__ Bh, const bf16* __restrict__ Bl,
    int row0, int col0, int k0, int Ktot, int tid)
{
    unsigned stb = sbase + (unsigned)(s * STG_EL * 2);
#pragma unroll
    for (int q = 0; q < 2; q++) {
        int idx = tid + 256 * q;            /* 0..511 */
        int r = idx >> 2, cc = idx & 3;
        unsigned so = (unsigned)((r * PADK + cc * 8) * 2);
        size_t ga = (size_t)(row0 + r) * Ktot + k0 + cc * 8;
        size_t gb = (size_t)(col0 + r) * Ktot + k0 + cc * 8;
        CP16(stb + 0 * TILE_EL * 2 + so, Ah + ga);
        CP16(stb + 1 * TILE_EL * 2 + so, Al + ga);
        CP16(stb + 2 * TILE_EL * 2 + so, Bh + gb);
        CP16(stb + 3 * TILE_EL * 2 + so, Bl + gb);
    }
}

__device__ __forceinline__ void emit2(int r, int col, float2 v,
                                      const float* __restrict__ bias, int relu,
                                      float* __restrict__ Cf, bf16* __restrict__ Ch,
                                      bf16* __restrict__ Cl, int Nld)
{
    if (bias) { v.x += bias[col]; v.y += bias[col + 1]; }
    if (relu) { v.x = fmaxf(v.x, 0.f); v.y = fmaxf(v.y, 0.f); }
    size_t o = (size_t)r * Nld + col;
    if (Cf) {
        *(float2*)(Cf + o) = v;
    } else {
        bf16 hx = __float2bfloat16(v.x), hy = __float2bfloat16(v.y);
        union { __nv_bfloat162 b; unsigned u; } H;
        H.b = __nv_bfloat162(hx, hy);
        *(unsigned*)(Ch + o) = H.u;
        *(unsigned*)(Cl + o) = pack2(v.x - __bfloat162float(hx),
                                     v.y - __bfloat162float(hy));
    }
}

__global__ __launch_bounds__(256, 1)
void mm_bf16(const bf16* __restrict__ Ah, const bf16* __restrict__ Al,
             const bf16* __restrict__ Bh, const bf16* __restrict__ Bl,
             const float* __restrict__ bias,
             float* __restrict__ Cf, bf16* __restrict__ Ch, bf16* __restrict__ Cl,
             int Ktot, int Nld, int relu)
{
    extern __shared__ char smem[];
    unsigned sbase = smem_u32(smem);
    int tid = threadIdx.x;
    int lane = tid & 31, wrp = tid >> 5;
    int wm = wrp & 3, wn = wrp >> 2;        /* warp grid 4(M) x 2(N) */
    int row0 = blockIdx.y * 128, col0 = blockIdx.x * 128;

    float c[2][8][4];
#pragma unroll
    for (int i = 0; i < 2; i++)
#pragma unroll
        for (int j = 0; j < 8; j++)
#pragma unroll
            for (int q = 0; q < 4; q++) c[i][j][q] = 0.f;

    int nk = Ktot >> 5;
    stage_load(sbase, 0, Ah, Al, Bh, Bl, row0, col0, 0, Ktot, tid);
    CP_COMMIT();

    for (int it = 0; it < nk; it++) {
        if (it + 1 < nk) {
            stage_load(sbase, (it + 1) & 1, Ah, Al, Bh, Bl, row0, col0,
                       (it + 1) << 5, Ktot, tid);
            CP_COMMIT();
            CP_WAIT1();
        } else {
            CP_WAIT0();
        }
        __syncthreads();

        unsigned stb = sbase + (unsigned)((it & 1) * STG_EL * 2);
        unsigned stAH = stb;
        unsigned stAL = stb + TILE_EL * 2;
        unsigned stBH = stb + 2 * TILE_EL * 2;
        unsigned stBL = stb + 3 * TILE_EL * 2;

#pragma unroll
        for (int ks = 0; ks < 2; ks++) {
            int kc = ks * 16;
            unsigned ah[2][4], al[2][4], bh[4][4], bl[4][4];
#pragma unroll
            for (int ma = 0; ma < 2; ma++) {
                int el = (wm * 32 + ma * 16 + (lane & 15)) * PADK
                       + kc + ((lane >> 4) << 3);
                LDSM4(ah[ma], stAH + el * 2);
                LDSM4(al[ma], stAL + el * 2);
            }
#pragma unroll
            for (int nb = 0; nb < 4; nb++) {
                int n = wn * 64 + nb * 16 + ((lane >> 4) << 3) + (lane & 7);
                int el = n * PADK + kc + (((lane >> 3) & 1) << 3);
                LDSM4(bh[nb], stBH + el * 2);
                LDSM4(bl[nb], stBL + el * 2);
            }
#pragma unroll
            for (int ma = 0; ma < 2; ma++)
#pragma unroll
                for (int na = 0; na < 8; na++) {
                    const unsigned* bph = &bh[na >> 1][(na & 1) * 2];
                    const unsigned* bpl = &bl[na >> 1][(na & 1) * 2];
                    MMA16816(c[ma][na], ah[ma], bph);
                    MMA16816(c[ma][na], ah[ma], bpl);
                    MMA16816(c[ma][na], al[ma], bph);
                }
        }
        __syncthreads();
    }

    /* epilogue: direct fragment stores */
#pragma unroll
    for (int ma = 0; ma < 2; ma++) {
        int r0 = row0 + wm * 32 + ma * 16 + (lane >> 2);
#pragma unroll
        for (int na = 0; na < 8; na++) {
            int col = col0 + wn * 64 + na * 8 + ((lane & 3) << 1);
            emit2(r0,     col, make_float2(c[ma][na][0], c[ma][na][1]),
                  bias, relu, Cf, Ch, Cl, Nld);
            emit2(r0 + 8, col, make_float2(c[ma][na][2], c[ma][na][3]),
                  bias, relu, Cf, Ch, Cl, Nld);
        }
    }
}

/* ------------------ fused GATv2 softmax-aggregation --------------------- */
__device__ __forceinline__ float lrelu(float x) { return x > 0.f ? x : NEG * x; }

template <int HEADS, int SPLIT>
__global__ void gat_agg(const float* __restrict__ xl, const float* __restrict__ xr,
                        const float* __restrict__ att, const float* __restrict__ bias,
                        float* __restrict__ outf, bf16* __restrict__ oh,
                        bf16* __restrict__ ol, int relu)
{
    int w = (blockIdx.x * blockDim.x + threadIdx.x) >> 5;
    int lane = threadIdx.x & 31;
    if (w >= N_NODES * HEADS) return;
    int dst = w / HEADS;
    int h   = w - dst * HEADS;
    const int D = HEADS * HID;
    int cb = h * HID + lane * 4;

    float4 a4 = *(const float4*)(att + h * HID + lane * 4);
    float4 r4 = *(const float4*)(xr + (size_t)dst * D + cb);

    float m = -1e30f, s = 0.f;
    float4 acc = make_float4(0.f, 0.f, 0.f, 0.f);

    int j = g_off[dst], end = g_off[dst + 1];
    for (; j < end; j++) {
        int src = g_srcs[j];
        float4 l4 = *(const float4*)(xl + (size_t)src * D + cb);
        float p = lrelu(l4.x + r4.x) * a4.x;
        p      += lrelu(l4.y + r4.y) * a4.y;
        p      += lrelu(l4.z + r4.z) * a4.z;
        p      += lrelu(l4.w + r4.w) * a4.w;
#pragma unroll
        for (int o = 16; o > 0; o >>= 1) p += __shfl_xor_sync(0xffffffffu, p, o);
        float mn = fmaxf(m, p);
        float cc = __expf(m - mn);
        float wg = __expf(p - mn);
        s = s * cc + wg;
        acc.x = acc.x * cc + wg * l4.x;
        acc.y = acc.y * cc + wg * l4.y;
        acc.z = acc.z * cc + wg * l4.z;
        acc.w = acc.w * cc + wg * l4.w;
        m = mn;
    }
    float inv = 1.f / (s + 1e-16f);
    float4 bb = *(const float4*)(bias + h * HID + lane * 4);
    float4 o4;
    o4.x = acc.x * inv + bb.x;
    o4.y = acc.y * inv + bb.y;
    o4.z = acc.z * inv + bb.z;
    o4.w = acc.w * inv + bb.w;
    if (relu) {
        o4.x = fmaxf(o4.x, 0.f); o4.y = fmaxf(o4.y, 0.f);
        o4.z = fmaxf(o4.z, 0.f); o4.w = fmaxf(o4.w, 0.f);
    }
    size_t oidx = (size_t)dst * D + cb;
    if (SPLIT) {
        split_store4(oh, ol, oidx, o4);
    } else {
        *(float4*)(outf + oidx) = o4;
    }
}

/* ------------------ final [N,128] @ [128,10] + b ------------------------ */
__global__ void k_out(const float* __restrict__ x2, const float* __restrict__ W,
                      const float* __restrict__ b, float* __restrict__ y)
{
    __shared__ float Ws[HID * 10];
    __shared__ float bs[10];
    for (int i = threadIdx.x; i < HID * 10; i += blockDim.x) Ws[i] = W[i];
    if (threadIdx.x < 10) bs[threadIdx.x] = b[threadIdx.x];
    __syncthreads();
    int w = (blockIdx.x * blockDim.x + threadIdx.x) >> 5;
    int lane = threadIdx.x & 31;
    if (w >= N_NODES) return;
    float4 v = *(const float4*)(x2 + (size_t)w * HID + lane * 4);
    int k = lane * 4;
    float p[10];
#pragma unroll
    for (int o = 0; o < 10; o++)
        p[o] = v.x * Ws[(k + 0) * 10 + o] + v.y * Ws[(k + 1) * 10 + o] +
               v.z * Ws[(k + 2) * 10 + o] + v.w * Ws[(k + 3) * 10 + o];
#pragma unroll
    for (int o = 0; o < 10; o++)
#pragma unroll
        for (int off = 16; off > 0; off >>= 1)
            p[o] += __shfl_xor_sync(0xffffffffu, p[o], off);
    if (lane < 10) y[(size_t)w * 10 + lane] = p[lane] + bs[lane];
}

/* ------------------ launch ---------------------------------------------- */
extern "C" void kernel_launch(void* const* d_in, const int* in_sizes, int n_in,
                              void* d_out, int out_size)
{
    const float* x_player   = (const float*)d_in[0];
    const int*   edge_index = (const int*)  d_in[1];
    const float* emb        = (const float*)d_in[2];
    const float* proj_W     = (const float*)d_in[3];
    const float* proj_b     = (const float*)d_in[4];
    const float* W1l        = (const float*)d_in[5];
    const float* W1r        = (const float*)d_in[6];
    const float* att1       = (const float*)d_in[7];
    const float* b1         = (const float*)d_in[8];
    const float* W2l        = (const float*)d_in[9];
    const float* W2r        = (const float*)d_in[10];
    const float* att2       = (const float*)d_in[11];
    const float* b2         = (const float*)d_in[12];
    const float* out_W      = (const float*)d_in[13];
    const float* out_b      = (const float*)d_in[14];
    float* y = (float*)d_out;

    bf16 *xinh, *xinl, *x0h, *x0l, *x1h, *x1l;
    bf16 *pWh, *pWl, *W1lh, *W1ll, *W1rh, *W1rl, *W2lh, *W2ll, *W2rh, *W2rl;
    float *xl1, *xr1, *xl2, *xr2, *x2;
    cudaGetSymbolAddress((void**)&xinh, g_xinh); cudaGetSymbolAddress((void**)&xinl, g_xinl);
    cudaGetSymbolAddress((void**)&x0h,  g_x0h);  cudaGetSymbolAddress((void**)&x0l,  g_x0l);
    cudaGetSymbolAddress((void**)&x1h,  g_x1h);  cudaGetSymbolAddress((void**)&x1l,  g_x1l);
    cudaGetSymbolAddress((void**)&xl1,  g_xl1);  cudaGetSymbolAddress((void**)&xr1,  g_xr1);
    cudaGetSymbolAddress((void**)&xl2,  g_xl2);  cudaGetSymbolAddress((void**)&xr2,  g_xr2);
    cudaGetSymbolAddress((void**)&x2,   g_x2);
    cudaGetSymbolAddress((void**)&pWh,  g_pWh);  cudaGetSymbolAddress((void**)&pWl,  g_pWl);
    cudaGetSymbolAddress((void**)&W1lh, g_W1lh); cudaGetSymbolAddress((void**)&W1ll, g_W1ll);
    cudaGetSymbolAddress((void**)&W1rh, g_W1rh); cudaGetSymbolAddress((void**)&W1rl, g_W1rl);
    cudaGetSymbolAddress((void**)&W2lh, g_W2lh); cudaGetSymbolAddress((void**)&W2ll, g_W2ll);
    cudaGetSymbolAddress((void**)&W2rh, g_W2rh); cudaGetSymbolAddress((void**)&W2rl, g_W2rl);

    cudaFuncSetAttribute(mm_bf16, cudaFuncAttributeMaxDynamicSharedMemorySize, SM_SZ);

    /* CSR build */
    k_init_deg<<<(N_NODES + 255) / 256, 256>>>();
    k_count   <<<(N_EDGES + 255) / 256, 256>>>(edge_index);
    k_scan    <<<1, 1024>>>();
    k_scatter <<<(N_EDGES + 255) / 256, 256>>>(edge_index);
    k_selfloop<<<(N_NODES + 255) / 256, 256>>>();

    /* gather + weight conversions */
    k_gather<<<(N_NODES * KIN + 255) / 256, 256>>>(x_player, emb);
    k_convw<<<(KIN * HID + 255) / 256, 256>>>(proj_W, pWh, pWl, KIN, HID);
    k_convw<<<(HID * 4 * HID + 255) / 256, 256>>>(W1l, W1lh, W1ll, HID, 4 * HID);
    k_convw<<<(HID * 4 * HID + 255) / 256, 256>>>(W1r, W1rh, W1rl, HID, 4 * HID);
    k_convw<<<(4 * HID * HID + 255) / 256, 256>>>(W2l, W2lh, W2ll, 4 * HID, HID);
    k_convw<<<(4 * HID * HID + 255) / 256, 256>>>(W2r, W2rh, W2rl, 4 * HID, HID);

    /* proj: [MPAD,192]@[192,128] + b, relu, split-output */
    mm_bf16<<<dim3(1, MPAD / 128), 256, SM_SZ>>>(
        xinh, xinl, pWh, pWl, proj_b, nullptr, x0h, x0l, KIN, HID, 1);

    /* GAT layer 1 linear (K=128, N=512) */
    mm_bf16<<<dim3(4, MPAD / 128), 256, SM_SZ>>>(
        x0h, x0l, W1lh, W1ll, nullptr, xl1, nullptr, nullptr, HID, 4 * HID, 0);
    mm_bf16<<<dim3(4, MPAD / 128), 256, SM_SZ>>>(
        x0h, x0l, W1rh, W1rl, nullptr, xr1, nullptr, nullptr, HID, 4 * HID, 0);
    gat_agg<4, 1><<<(N_NODES * 4 * 32 + 255) / 256, 256>>>(
        xl1, xr1, att1, b1, nullptr, x1h, x1l, 1);

    /* GAT layer 2 linear (K=512, N=128) */
    mm_bf16<<<dim3(1, MPAD / 128), 256, SM_SZ>>>(
        x1h, x1l, W2lh, W2ll, nullptr, xl2, nullptr, nullptr, 4 * HID, HID, 0);
    mm_bf16<<<dim3(1, MPAD / 128), 256, SM_SZ>>>(
        x1h, x1l, W2rh, W2rl, nullptr, xr2, nullptr, nullptr, 4 * HID, HID, 0);
    gat_agg<1, 0><<<(N_NODES * 32 + 255) / 256, 256>>>(
        xl2, xr2, att2, b2, x2, nullptr, nullptr, 0);

    /* output projection */
    k_out<<<(N_NODES * 32 + 255) / 256, 256>>>(x2, out_W, out_b, y);
}

// round 6
// speedup vs baseline: 1.7507x; 1.1182x over previous
#include <cuda_runtime.h>
#include <cuda_bf16.h>
#include <stdint.h>
#include <math.h>

#define N_NODES 20000
#define MPAD    20096          /* 157 * 128 */
#define N_EDGES 320000
#define ETOT    (N_EDGES + N_NODES)
#define FEAT    64
#define HID     128
#define KIN     (HID + FEAT)   /* 192 */
#define NEG     0.2f

typedef __nv_bfloat16 bf16;

/* ------------------ scratch (device globals) ----------------------------- */
__device__ __align__(256) bf16  g_xinh[MPAD * KIN];
__device__ __align__(256) bf16  g_xinl[MPAD * KIN];
__device__ __align__(256) bf16  g_x0h [MPAD * HID];
__device__ __align__(256) bf16  g_x0l [MPAD * HID];
__device__ __align__(256) float g_xlr1[MPAD * 1024];     /* [xl1(512)|xr1(512)] */
__device__ __align__(256) bf16  g_x1h [MPAD * 4 * HID];
__device__ __align__(256) bf16  g_x1l [MPAD * 4 * HID];
__device__ __align__(256) float g_xlr2[MPAD * 256];      /* [xl2(128)|xr2(128)] */
__device__ __align__(256) float g_x2  [MPAD * HID];
/* merged transposed split weights: [N,K] K-major */
__device__ __align__(256) bf16  g_pWh [HID * KIN],   g_pWl [HID * KIN];
__device__ __align__(256) bf16  g_W1h [1024 * HID],  g_W1l [1024 * HID];
__device__ __align__(256) bf16  g_W2h [256 * 4 * HID], g_W2l [256 * 4 * HID];
__device__ int   g_deg[N_NODES];
__device__ int   g_off[N_NODES + 1];
__device__ int   g_cur[N_NODES];
__device__ int   g_srcs[ETOT];

/* ------------------ pack helpers ---------------------------------------- */
__device__ __forceinline__ unsigned int pack2(float a, float b) {
    union { __nv_bfloat162 v; unsigned int u; } c;
    c.v = __nv_bfloat162(__float2bfloat16(a), __float2bfloat16(b));
    return c.u;
}
__device__ __forceinline__ void split_store4(bf16* hp, bf16* lp, size_t o, float4 v) {
    bf16 hx = __float2bfloat16(v.x), hy = __float2bfloat16(v.y);
    bf16 hz = __float2bfloat16(v.z), hw = __float2bfloat16(v.w);
    union { __nv_bfloat162 v; unsigned int u; } a, b;
    a.v = __nv_bfloat162(hx, hy); b.v = __nv_bfloat162(hz, hw);
    *(uint2*)(hp + o) = make_uint2(a.u, b.u);
    *(uint2*)(lp + o) = make_uint2(
        pack2(v.x - __bfloat162float(hx), v.y - __bfloat162float(hy)),
        pack2(v.z - __bfloat162float(hz), v.w - __bfloat162float(hw)));
}

/* ------------------ PTX helpers (baseline sm_80+) ------------------------ */
__device__ __forceinline__ unsigned int smem_u32(const void* p) {
    unsigned int a;
    asm("{ .reg .u64 t; cvta.to.shared.u64 t, %1; cvt.u32.u64 %0, t; }" : "=r"(a) : "l"(p));
    return a;
}
#define CP16(dst, src)  asm volatile("cp.async.ca.shared.global [%0], [%1], 16;" :: "r"(dst), "l"(src) : "memory")
#define CP_COMMIT()     asm volatile("cp.async.commit_group;" ::: "memory")
#define CP_WAIT1()      asm volatile("cp.async.wait_group 1;" ::: "memory")
#define CP_WAIT0()      asm volatile("cp.async.wait_group 0;" ::: "memory")

#define LDSM4(d, addr) \
    asm volatile("ldmatrix.sync.aligned.m8n8.x4.shared.b16 {%0,%1,%2,%3}, [%4];" \
        : "=r"((d)[0]), "=r"((d)[1]), "=r"((d)[2]), "=r"((d)[3]) : "r"(addr))

#define MMA16816(c, a, b) \
    asm volatile("mma.sync.aligned.m16n8k16.row.col.f32.bf16.bf16.f32 " \
        "{%0,%1,%2,%3}, {%4,%5,%6,%7}, {%8,%9}, {%0,%1,%2,%3};" \
        : "+f"((c)[0]), "+f"((c)[1]), "+f"((c)[2]), "+f"((c)[3]) \
        : "r"((a)[0]), "r"((a)[1]), "r"((a)[2]), "r"((a)[3]), \
          "r"((b)[0]), "r"((b)[1]))

/* ------------------ CSR build ------------------------------------------- */
__global__ void k_init_deg() {
    int i = blockIdx.x * blockDim.x + threadIdx.x;
    if (i < N_NODES) g_deg[i] = 1;            /* self loop */
}
__global__ void k_count(const int* __restrict__ ei) {
    int e = blockIdx.x * blockDim.x + threadIdx.x;
    if (e < N_EDGES) atomicAdd(&g_deg[ei[N_EDGES + e]], 1);
}
/* scan + place self-loop at segment head (order within segment is free) */
__global__ void k_scan() {
    __shared__ int ps[1024];
    int t = threadIdx.x;
    const int CH = (N_NODES + 1023) / 1024;
    int base = t * CH, s = 0;
    for (int i = 0; i < CH; i++) { int idx = base + i; if (idx < N_NODES) s += g_deg[idx]; }
    ps[t] = s;
    __syncthreads();
    for (int off = 1; off < 1024; off <<= 1) {
        int v = (t >= off) ? ps[t - off] : 0;
        __syncthreads();
        ps[t] += v;
        __syncthreads();
    }
    int run = ps[t] - s;
    for (int i = 0; i < CH; i++) {
        int idx = base + i;
        if (idx < N_NODES) {
            g_off[idx] = run;
            g_srcs[run] = idx;                /* self loop first */
            g_cur[idx] = run + 1;
            run += g_deg[idx];
        }
    }
    if (t == 1023) g_off[N_NODES] = ps[1023];
}
__global__ void k_scatter(const int* __restrict__ ei) {
    int e = blockIdx.x * blockDim.x + threadIdx.x;
    if (e < N_EDGES) {
        int d = ei[N_EDGES + e];
        int p = atomicAdd(&g_cur[d], 1);
        g_srcs[p] = ei[e];
    }
}

/* ------------------ input gather -> split bf16 --------------------------- */
__device__ __forceinline__ void split_store(bf16* h, bf16* l, size_t idx, float v) {
    bf16 hb = __float2bfloat16(v);
    h[idx] = hb;
    l[idx] = __float2bfloat16(v - __bfloat162float(hb));
}

__global__ void k_gather(const float* __restrict__ xp, const float* __restrict__ emb) {
    int idx = blockIdx.x * blockDim.x + threadIdx.x;
    if (idx >= N_NODES * KIN) return;
    int i = idx / KIN, k = idx - i * KIN;
    float v;
    if (k < HID) {
        int id = (int)xp[i * (FEAT + 1)];
        v = emb[id * HID + k];
    } else {
        v = xp[i * (FEAT + 1) + 1 + (k - HID)];
    }
    split_store(g_xinh, g_xinl, (size_t)i * KIN + k, v);
}

/* ------------------ weight transpose + split: [K,N] -> [N,K] ------------- */
__global__ void k_convw(const float* __restrict__ W, bf16* __restrict__ h,
                        bf16* __restrict__ l, int K, int N) {
    int idx = blockIdx.x * blockDim.x + threadIdx.x;
    if (idx >= K * N) return;
    int k = idx / N, n = idx - k * N;
    split_store(h, l, (size_t)n * K + k, W[(size_t)k * N + n]);
}

/* ------------------ HMMA split-bf16 GEMM --------------------------------- */
/* C[M=MPAD, Ntot] = A[M,Ktot] @ B^T (B stored [Ntot,Ktot] K-major)          */
/* CTA 128x128, BK=64, 8 warps (4M x 2N), warp tile 32x64.                   */
#define PADK   72                       /* 64 elems + 8 pad per smem row */
#define TILE_EL (128 * PADK)            /* 9216 elems */
#define STG_B   (4 * TILE_EL * 2)       /* 73728 bytes per stage */
#define SM_SZ   (2 * STG_B)             /* 147456 bytes */

__device__ __forceinline__ void stage_load(
    unsigned sbase, int s,
    const bf16* __restrict__ Ah, const bf16* __restrict__ Al,
    const bf16* __restrict__ Bh, const bf16* __restrict__ Bl,
    int row0, int col0, int k0, int Ktot, int tid)
{
    unsigned stb = sbase + (unsigned)(s * STG_B);
#pragma unroll
    for (int q = 0; q < 4; q++) {
        int idx = tid + 256 * q;            /* 0..1023 */
        int r = idx >> 3, cc = idx & 7;
        unsigned so = (unsigned)((r * PADK + cc * 8) * 2);
        size_t ga = (size_t)(row0 + r) * Ktot + k0 + cc * 8;
        size_t gb = (size_t)(col0 + r) * Ktot + k0 + cc * 8;
        CP16(stb + 0 * TILE_EL * 2 + so, Ah + ga);
        CP16(stb + 1 * TILE_EL * 2 + so, Al + ga);
        CP16(stb + 2 * TILE_EL * 2 + so, Bh + gb);
        CP16(stb + 3 * TILE_EL * 2 + so, Bl + gb);
    }
}

__device__ __forceinline__ void emit2(int r, int col, float2 v,
                                      const float* __restrict__ bias, int relu,
                                      float* __restrict__ Cf, bf16* __restrict__ Ch,
                                      bf16* __restrict__ Cl, int Nld)
{
    if (bias) { v.x += bias[col]; v.y += bias[col + 1]; }
    if (relu) { v.x = fmaxf(v.x, 0.f); v.y = fmaxf(v.y, 0.f); }
    size_t o = (size_t)r * Nld + col;
    if (Cf) {
        *(float2*)(Cf + o) = v;
    } else {
        bf16 hx = __float2bfloat16(v.x), hy = __float2bfloat16(v.y);
        union { __nv_bfloat162 b; unsigned u; } H;
        H.b = __nv_bfloat162(hx, hy);
        *(unsigned*)(Ch + o) = H.u;
        *(unsigned*)(Cl + o) = pack2(v.x - __bfloat162float(hx),
                                     v.y - __bfloat162float(hy));
    }
}

__global__ __launch_bounds__(256, 1)
void mm_bf16(const bf16* __restrict__ Ah, const bf16* __restrict__ Al,
             const bf16* __restrict__ Bh, const bf16* __restrict__ Bl,
             const float* __restrict__ bias,
             float* __restrict__ Cf, bf16* __restrict__ Ch, bf16* __restrict__ Cl,
             int Ktot, int Nld, int relu)
{
    extern __shared__ char smem[];
    unsigned sbase = smem_u32(smem);
    int tid = threadIdx.x;
    int lane = tid & 31, wrp = tid >> 5;
    int wm = wrp & 3, wn = wrp >> 2;        /* warp grid 4(M) x 2(N) */
    int row0 = blockIdx.y * 128, col0 = blockIdx.x * 128;

    float c[2][8][4];
#pragma unroll
    for (int i = 0; i < 2; i++)
#pragma unroll
        for (int j = 0; j < 8; j++)
#pragma unroll
            for (int q = 0; q < 4; q++) c[i][j][q] = 0.f;

    int nk = Ktot >> 6;
    stage_load(sbase, 0, Ah, Al, Bh, Bl, row0, col0, 0, Ktot, tid);
    CP_COMMIT();

    for (int it = 0; it < nk; it++) {
        if (it + 1 < nk) {
            stage_load(sbase, (it + 1) & 1, Ah, Al, Bh, Bl, row0, col0,
                       (it + 1) << 6, Ktot, tid);
            CP_COMMIT();
            CP_WAIT1();
        } else {
            CP_WAIT0();
        }
        __syncthreads();

        unsigned stb = sbase + (unsigned)((it & 1) * STG_B);
        unsigned stAH = stb;
        unsigned stAL = stb + TILE_EL * 2;
        unsigned stBH = stb + 2 * TILE_EL * 2;
        unsigned stBL = stb + 3 * TILE_EL * 2;

#pragma unroll
        for (int ks = 0; ks < 4; ks++) {
            int kc = ks * 16;
            unsigned ah[2][4], al[2][4], bh[4][4], bl[4][4];
#pragma unroll
            for (int ma = 0; ma < 2; ma++) {
                int el = (wm * 32 + ma * 16 + (lane & 15)) * PADK
                       + kc + ((lane >> 4) << 3);
                LDSM4(ah[ma], stAH + el * 2);
                LDSM4(al[ma], stAL + el * 2);
            }
#pragma unroll
            for (int nb = 0; nb < 4; nb++) {
                int n = wn * 64 + nb * 16 + ((lane >> 4) << 3) + (lane & 7);
                int el = n * PADK + kc + (((lane >> 3) & 1) << 3);
                LDSM4(bh[nb], stBH + el * 2);
                LDSM4(bl[nb], stBL + el * 2);
            }
#pragma unroll
            for (int ma = 0; ma < 2; ma++)
#pragma unroll
                for (int na = 0; na < 8; na++) {
                    const unsigned* bph = &bh[na >> 1][(na & 1) * 2];
                    const unsigned* bpl = &bl[na >> 1][(na & 1) * 2];
                    MMA16816(c[ma][na], ah[ma], bph);
                    MMA16816(c[ma][na], ah[ma], bpl);
                    MMA16816(c[ma][na], al[ma], bph);
                }
        }
        __syncthreads();
    }

#pragma unroll
    for (int ma = 0; ma < 2; ma++) {
        int r0 = row0 + wm * 32 + ma * 16 + (lane >> 2);
#pragma unroll
        for (int na = 0; na < 8; na++) {
            int col = col0 + wn * 64 + na * 8 + ((lane & 3) << 1);
            emit2(r0,     col, make_float2(c[ma][na][0], c[ma][na][1]),
                  bias, relu, Cf, Ch, Cl, Nld);
            emit2(r0 + 8, col, make_float2(c[ma][na][2], c[ma][na][3]),
                  bias, relu, Cf, Ch, Cl, Nld);
        }
    }
}

/* ------------------ fused GATv2 softmax-aggregation --------------------- */
/* xl/xr share rows of one interleaved buffer with row stride D.            */
__device__ __forceinline__ float lrelu(float x) { return x > 0.f ? x : NEG * x; }

template <int HEADS, int SPLIT, int D>
__global__ void gat_agg(const float* __restrict__ xl, const float* __restrict__ xr,
                        const float* __restrict__ att, const float* __restrict__ bias,
                        float* __restrict__ outf, bf16* __restrict__ oh,
                        bf16* __restrict__ ol, int relu)
{
    int w = (blockIdx.x * blockDim.x + threadIdx.x) >> 5;
    int lane = threadIdx.x & 31;
    if (w >= N_NODES * HEADS) return;
    int dst = w / HEADS;
    int h   = w - dst * HEADS;
    int cb = h * HID + lane * 4;

    float4 a4 = *(const float4*)(att + h * HID + lane * 4);
    float4 r4 = *(const float4*)(xr + (size_t)dst * D + cb);

    float m = -1e30f, s = 0.f;
    float4 acc = make_float4(0.f, 0.f, 0.f, 0.f);

    int j = g_off[dst], end = g_off[dst + 1];
    int src = g_srcs[j];
    for (; j < end; j++) {
        int nsrc = (j + 1 < end) ? g_srcs[j + 1] : 0;
        float4 l4 = *(const float4*)(xl + (size_t)src * D + cb);
        src = nsrc;
        float p = lrelu(l4.x + r4.x) * a4.x;
        p      += lrelu(l4.y + r4.y) * a4.y;
        p      += lrelu(l4.z + r4.z) * a4.z;
        p      += lrelu(l4.w + r4.w) * a4.w;
#pragma unroll
        for (int o = 16; o > 0; o >>= 1) p += __shfl_xor_sync(0xffffffffu, p, o);
        float mn = fmaxf(m, p);
        float cc = __expf(m - mn);
        float wg = __expf(p - mn);
        s = s * cc + wg;
        acc.x = acc.x * cc + wg * l4.x;
        acc.y = acc.y * cc + wg * l4.y;
        acc.z = acc.z * cc + wg * l4.z;
        acc.w = acc.w * cc + wg * l4.w;
        m = mn;
    }
    float inv = 1.f / (s + 1e-16f);
    float4 bb = *(const float4*)(bias + h * HID + lane * 4);
    float4 o4;
    o4.x = acc.x * inv + bb.x;
    o4.y = acc.y * inv + bb.y;
    o4.z = acc.z * inv + bb.z;
    o4.w = acc.w * inv + bb.w;
    if (relu) {
        o4.x = fmaxf(o4.x, 0.f); o4.y = fmaxf(o4.y, 0.f);
        o4.z = fmaxf(o4.z, 0.f); o4.w = fmaxf(o4.w, 0.f);
    }
    size_t oidx = (size_t)dst * (HEADS * HID) + cb;
    if (SPLIT) {
        split_store4(oh, ol, oidx, o4);
    } else {
        *(float4*)(outf + oidx) = o4;
    }
}

/* ------------------ final [N,128] @ [128,10] + b ------------------------ */
__global__ void k_out(const float* __restrict__ x2, const float* __restrict__ W,
                      const float* __restrict__ b, float* __restrict__ y)
{
    __shared__ float Ws[HID * 10];
    __shared__ float bs[10];
    for (int i = threadIdx.x; i < HID * 10; i += blockDim.x) Ws[i] = W[i];
    if (threadIdx.x < 10) bs[threadIdx.x] = b[threadIdx.x];
    __syncthreads();
    int w = (blockIdx.x * blockDim.x + threadIdx.x) >> 5;
    int lane = threadIdx.x & 31;
    if (w >= N_NODES) return;
    float4 v = *(const float4*)(x2 + (size_t)w * HID + lane * 4);
    int k = lane * 4;
    float p[10];
#pragma unroll
    for (int o = 0; o < 10; o++)
        p[o] = v.x * Ws[(k + 0) * 10 + o] + v.y * Ws[(k + 1) * 10 + o] +
               v.z * Ws[(k + 2) * 10 + o] + v.w * Ws[(k + 3) * 10 + o];
#pragma unroll
    for (int o = 0; o < 10; o++)
#pragma unroll
        for (int off = 16; off > 0; off >>= 1)
            p[o] += __shfl_xor_sync(0xffffffffu, p[o], off);
    if (lane < 10) y[(size_t)w * 10 + lane] = p[lane] + bs[lane];
}

/* ------------------ launch ---------------------------------------------- */
extern "C" void kernel_launch(void* const* d_in, const int* in_sizes, int n_in,
                              void* d_out, int out_size)
{
    const float* x_player   = (const float*)d_in[0];
    const int*   edge_index = (const int*)  d_in[1];
    const float* emb        = (const float*)d_in[2];
    const float* proj_W     = (const float*)d_in[3];
    const float* proj_b     = (const float*)d_in[4];
    const float* W1l        = (const float*)d_in[5];
    const float* W1r        = (const float*)d_in[6];
    const float* att1       = (const float*)d_in[7];
    const float* b1         = (const float*)d_in[8];
    const float* W2l        = (const float*)d_in[9];
    const float* W2r        = (const float*)d_in[10];
    const float* att2       = (const float*)d_in[11];
    const float* b2         = (const float*)d_in[12];
    const float* out_W      = (const float*)d_in[13];
    const float* out_b      = (const float*)d_in[14];
    float* y = (float*)d_out;

    bf16 *xinh, *xinl, *x0h, *x0l, *x1h, *x1l;
    bf16 *pWh, *pWl, *W1h, *W1lo, *W2h, *W2lo;
    float *xlr1, *xlr2, *x2;
    cudaGetSymbolAddress((void**)&xinh, g_xinh); cudaGetSymbolAddress((void**)&xinl, g_xinl);
    cudaGetSymbolAddress((void**)&x0h,  g_x0h);  cudaGetSymbolAddress((void**)&x0l,  g_x0l);
    cudaGetSymbolAddress((void**)&x1h,  g_x1h);  cudaGetSymbolAddress((void**)&x1l,  g_x1l);
    cudaGetSymbolAddress((void**)&xlr1, g_xlr1); cudaGetSymbolAddress((void**)&xlr2, g_xlr2);
    cudaGetSymbolAddress((void**)&x2,   g_x2);
    cudaGetSymbolAddress((void**)&pWh,  g_pWh);  cudaGetSymbolAddress((void**)&pWl,  g_pWl);
    cudaGetSymbolAddress((void**)&W1h,  g_W1h);  cudaGetSymbolAddress((void**)&W1lo, g_W1l);
    cudaGetSymbolAddress((void**)&W2h,  g_W2h);  cudaGetSymbolAddress((void**)&W2lo, g_W2l);

    cudaFuncSetAttribute(mm_bf16, cudaFuncAttributeMaxDynamicSharedMemorySize, SM_SZ);

    /* CSR build (self-loops placed in k_scan) */
    k_init_deg<<<(N_NODES + 255) / 256, 256>>>();
    k_count   <<<(N_EDGES + 255) / 256, 256>>>(edge_index);
    k_scan    <<<1, 1024>>>();
    k_scatter <<<(N_EDGES + 255) / 256, 256>>>(edge_index);

    /* gather + weight conversions (merged l|r buffers) */
    k_gather<<<(N_NODES * KIN + 255) / 256, 256>>>(x_player, emb);
    k_convw<<<(KIN * HID + 255) / 256, 256>>>(proj_W, pWh, pWl, KIN, HID);
    k_convw<<<(HID * 512 + 255) / 256, 256>>>(W1l, W1h,             W1lo,             HID, 512);
    k_convw<<<(HID * 512 + 255) / 256, 256>>>(W1r, W1h + 512 * HID, W1lo + 512 * HID, HID, 512);
    k_convw<<<(512 * HID + 255) / 256, 256>>>(W2l, W2h,             W2lo,             512, HID);
    k_convw<<<(512 * HID + 255) / 256, 256>>>(W2r, W2h + 128 * 512, W2lo + 128 * 512, 512, HID);

    /* proj: [MPAD,192]@[192,128] + b, relu, split-output */
    mm_bf16<<<dim3(1, MPAD / 128), 256, SM_SZ>>>(
        xinh, xinl, pWh, pWl, proj_b, nullptr, x0h, x0l, KIN, HID, 1);

    /* GAT layer 1 linear: one merged GEMM N=1024 -> [xl|xr] rows */
    mm_bf16<<<dim3(8, MPAD / 128), 256, SM_SZ>>>(
        x0h, x0l, W1h, W1lo, nullptr, xlr1, nullptr, nullptr, HID, 1024, 0);
    gat_agg<4, 1, 1024><<<(N_NODES * 4 * 32 + 255) / 256, 256>>>(
        xlr1, xlr1 + 512, att1, b1, nullptr, x1h, x1l, 1);

    /* GAT layer 2 linear: merged GEMM N=256 */
    mm_bf16<<<dim3(2, MPAD / 128), 256, SM_SZ>>>(
        x1h, x1l, W2h, W2lo, nullptr, xlr2, nullptr, nullptr, 512, 256, 0);
    gat_agg<1, 0, 256><<<(N_NODES * 32 + 255) / 256, 256>>>(
        xlr2, xlr2 + 128, att2, b2, x2, nullptr, nullptr, 0);

    /* output projection */
    k_out<<<(N_NODES * 32 + 255) / 256, 256>>>(x2, out_W, out_b, y);
}

// round 7
// speedup vs baseline: 1.7950x; 1.0253x over previous
#include <cuda_runtime.h>
#include <cuda_bf16.h>
#include <stdint.h>
#include <math.h>

#define N_NODES 20000
#define MPAD    20096          /* 157 * 128, also /64 = 314 */
#define N_EDGES 320000
#define ETOT    (N_EDGES + N_NODES)
#define FEAT    64
#define HID     128
#define KIN     (HID + FEAT)   /* 192 */
#define NEG     0.2f

typedef __nv_bfloat16 bf16;

/* ------------------ scratch (device globals) ----------------------------- */
__device__ __align__(256) bf16  g_xinh[MPAD * KIN];
__device__ __align__(256) bf16  g_xinl[MPAD * KIN];
__device__ __align__(256) bf16  g_x0h [MPAD * HID];
__device__ __align__(256) bf16  g_x0l [MPAD * HID];
__device__ __align__(256) float g_xlr1[MPAD * 1024];     /* [xl1(512)|xr1(512)] */
__device__ __align__(256) bf16  g_x1h [MPAD * 4 * HID];
__device__ __align__(256) bf16  g_x1l [MPAD * 4 * HID];
__device__ __align__(256) float g_xlr2[MPAD * 256];      /* [xl2(128)|xr2(128)] */
/* merged transposed split weights: [N,K] K-major */
__device__ __align__(256) bf16  g_pWh [HID * KIN],   g_pWl [HID * KIN];
__device__ __align__(256) bf16  g_W1h [1024 * HID],  g_W1l [1024 * HID];
__device__ __align__(256) bf16  g_W2h [256 * 4 * HID], g_W2l [256 * 4 * HID];
__device__ int   g_deg[N_NODES];
__device__ int   g_off[N_NODES + 1];
__device__ int   g_cur[N_NODES];
__device__ int   g_srcs[ETOT];

/* ------------------ pack helpers ---------------------------------------- */
__device__ __forceinline__ unsigned int pack2(float a, float b) {
    union { __nv_bfloat162 v; unsigned int u; } c;
    c.v = __nv_bfloat162(__float2bfloat16(a), __float2bfloat16(b));
    return c.u;
}
__device__ __forceinline__ void split_store4(bf16* hp, bf16* lp, size_t o, float4 v) {
    bf16 hx = __float2bfloat16(v.x), hy = __float2bfloat16(v.y);
    bf16 hz = __float2bfloat16(v.z), hw = __float2bfloat16(v.w);
    union { __nv_bfloat162 v; unsigned int u; } a, b;
    a.v = __nv_bfloat162(hx, hy); b.v = __nv_bfloat162(hz, hw);
    *(uint2*)(hp + o) = make_uint2(a.u, b.u);
    *(uint2*)(lp + o) = make_uint2(
        pack2(v.x - __bfloat162float(hx), v.y - __bfloat162float(hy)),
        pack2(v.z - __bfloat162float(hz), v.w - __bfloat162float(hw)));
}

/* ------------------ PTX helpers (baseline sm_80+) ------------------------ */
__device__ __forceinline__ unsigned int smem_u32(const void* p) {
    unsigned int a;
    asm("{ .reg .u64 t; cvta.to.shared.u64 t, %1; cvt.u32.u64 %0, t; }" : "=r"(a) : "l"(p));
    return a;
}
#define CP16(dst, src)  asm volatile("cp.async.ca.shared.global [%0], [%1], 16;" :: "r"(dst), "l"(src) : "memory")
#define CP_COMMIT()     asm volatile("cp.async.commit_group;" ::: "memory")
#define CP_WAIT1()      asm volatile("cp.async.wait_group 1;" ::: "memory")
#define CP_WAIT0()      asm volatile("cp.async.wait_group 0;" ::: "memory")

#define LDSM4(d, addr) \
    asm volatile("ldmatrix.sync.aligned.m8n8.x4.shared.b16 {%0,%1,%2,%3}, [%4];" \
        : "=r"((d)[0]), "=r"((d)[1]), "=r"((d)[2]), "=r"((d)[3]) : "r"(addr))

#define MMA16816(c, a, b) \
    asm volatile("mma.sync.aligned.m16n8k16.row.col.f32.bf16.bf16.f32 " \
        "{%0,%1,%2,%3}, {%4,%5,%6,%7}, {%8,%9}, {%0,%1,%2,%3};" \
        : "+f"((c)[0]), "+f"((c)[1]), "+f"((c)[2]), "+f"((c)[3]) \
        : "r"((a)[0]), "r"((a)[1]), "r"((a)[2]), "r"((a)[3]), \
          "r"((b)[0]), "r"((b)[1]))

/* ------------------ CSR build ------------------------------------------- */
__global__ void k_init_deg() {
    int i = blockIdx.x * blockDim.x + threadIdx.x;
    if (i < N_NODES) g_deg[i] = 1;            /* self loop */
}
__global__ void k_count(const int* __restrict__ ei) {
    int e = blockIdx.x * blockDim.x + threadIdx.x;
    if (e < N_EDGES) atomicAdd(&g_deg[ei[N_EDGES + e]], 1);
}
__global__ void k_scan() {
    __shared__ int ps[1024];
    int t = threadIdx.x;
    const int CH = (N_NODES + 1023) / 1024;
    int base = t * CH, s = 0;
    for (int i = 0; i < CH; i++) { int idx = base + i; if (idx < N_NODES) s += g_deg[idx]; }
    ps[t] = s;
    __syncthreads();
    for (int off = 1; off < 1024; off <<= 1) {
        int v = (t >= off) ? ps[t - off] : 0;
        __syncthreads();
        ps[t] += v;
        __syncthreads();
    }
    int run = ps[t] - s;
    for (int i = 0; i < CH; i++) {
        int idx = base + i;
        if (idx < N_NODES) {
            g_off[idx] = run;
            g_srcs[run] = idx;                /* self loop first */
            g_cur[idx] = run + 1;
            run += g_deg[idx];
        }
    }
    if (t == 1023) g_off[N_NODES] = ps[1023];
}
__global__ void k_scatter(const int* __restrict__ ei) {
    int e = blockIdx.x * blockDim.x + threadIdx.x;
    if (e < N_EDGES) {
        int d = ei[N_EDGES + e];
        int p = atomicAdd(&g_cur[d], 1);
        g_srcs[p] = ei[e];
    }
}

/* ------------------ input gather -> split bf16 --------------------------- */
__device__ __forceinline__ void split_store(bf16* h, bf16* l, size_t idx, float v) {
    bf16 hb = __float2bfloat16(v);
    h[idx] = hb;
    l[idx] = __float2bfloat16(v - __bfloat162float(hb));
}

__global__ void k_gather(const float* __restrict__ xp, const float* __restrict__ emb) {
    int idx = blockIdx.x * blockDim.x + threadIdx.x;
    if (idx >= N_NODES * KIN) return;
    int i = idx / KIN, k = idx - i * KIN;
    float v;
    if (k < HID) {
        int id = (int)xp[i * (FEAT + 1)];
        v = emb[id * HID + k];
    } else {
        v = xp[i * (FEAT + 1) + 1 + (k - HID)];
    }
    split_store(g_xinh, g_xinl, (size_t)i * KIN + k, v);
}

/* ------------------ weight transpose + split: [K,N] -> [N,K] ------------- */
__global__ void k_convw(const float* __restrict__ W, bf16* __restrict__ h,
                        bf16* __restrict__ l, int K, int N) {
    int idx = blockIdx.x * blockDim.x + threadIdx.x;
    if (idx >= K * N) return;
    int k = idx / N, n = idx - k * N;
    split_store(h, l, (size_t)n * K + k, W[(size_t)k * N + n]);
}

/* ------------------ HMMA split-bf16 GEMM --------------------------------- */
/* C[M=MPAD, Ntot] = A[M,Ktot] @ B^T (B stored [Ntot,Ktot] K-major)          */
/* CTA 64x128, BK=64, 8 warps (2M x 4N), warp tile 32x32, occ 2.             */
#define PADK    72                      /* 64 elems + 8 pad per smem row */
#define A_EL    (64 * PADK)             /* 4608 */
#define B_EL    (128 * PADK)            /* 9216 */
#define OFF_AH  0
#define OFF_AL  (A_EL * 2)
#define OFF_BH  (2 * A_EL * 2)
#define OFF_BL  (2 * A_EL * 2 + B_EL * 2)
#define STG_B   ((2 * A_EL + 2 * B_EL) * 2)   /* 55296 bytes */
#define SM_SZ   (2 * STG_B)                   /* 110592 bytes */

__device__ __forceinline__ void stage_load(
    unsigned sbase, int s,
    const bf16* __restrict__ Ah, const bf16* __restrict__ Al,
    const bf16* __restrict__ Bh, const bf16* __restrict__ Bl,
    int row0, int col0, int k0, int Ktot, int tid)
{
    unsigned stb = sbase + (unsigned)(s * STG_B);
#pragma unroll
    for (int q = 0; q < 2; q++) {           /* A: 64 rows x 8 chunks */
        int idx = tid + 256 * q;
        int r = idx >> 3, cc = idx & 7;
        unsigned so = (unsigned)((r * PADK + cc * 8) * 2);
        size_t ga = (size_t)(row0 + r) * Ktot + k0 + cc * 8;
        CP16(stb + OFF_AH + so, Ah + ga);
        CP16(stb + OFF_AL + so, Al + ga);
    }
#pragma unroll
    for (int q = 0; q < 4; q++) {           /* B: 128 rows x 8 chunks */
        int idx = tid + 256 * q;
        int r = idx >> 3, cc = idx & 7;
        unsigned so = (unsigned)((r * PADK + cc * 8) * 2);
        size_t gb = (size_t)(col0 + r) * Ktot + k0 + cc * 8;
        CP16(stb + OFF_BH + so, Bh + gb);
        CP16(stb + OFF_BL + so, Bl + gb);
    }
}

__device__ __forceinline__ void emit2(int r, int col, float2 v,
                                      const float* __restrict__ bias, int relu,
                                      float* __restrict__ Cf, bf16* __restrict__ Ch,
                                      bf16* __restrict__ Cl, int Nld)
{
    if (bias) { v.x += bias[col]; v.y += bias[col + 1]; }
    if (relu) { v.x = fmaxf(v.x, 0.f); v.y = fmaxf(v.y, 0.f); }
    size_t o = (size_t)r * Nld + col;
    if (Cf) {
        *(float2*)(Cf + o) = v;
    } else {
        bf16 hx = __float2bfloat16(v.x), hy = __float2bfloat16(v.y);
        union { __nv_bfloat162 b; unsigned u; } H;
        H.b = __nv_bfloat162(hx, hy);
        *(unsigned*)(Ch + o) = H.u;
        *(unsigned*)(Cl + o) = pack2(v.x - __bfloat162float(hx),
                                     v.y - __bfloat162float(hy));
    }
}

__global__ __launch_bounds__(256, 2)
void mm_bf16(const bf16* __restrict__ Ah, const bf16* __restrict__ Al,
             const bf16* __restrict__ Bh, const bf16* __restrict__ Bl,
             const float* __restrict__ bias,
             float* __restrict__ Cf, bf16* __restrict__ Ch, bf16* __restrict__ Cl,
             int Ktot, int Nld, int relu)
{
    extern __shared__ char smem[];
    unsigned sbase = smem_u32(smem);
    int tid = threadIdx.x;
    int lane = tid & 31, wrp = tid >> 5;
    int wm = wrp & 1, wn = wrp >> 1;        /* warp grid 2(M) x 4(N) */
    int row0 = blockIdx.y * 64, col0 = blockIdx.x * 128;

    float c[2][4][4];
#pragma unroll
    for (int i = 0; i < 2; i++)
#pragma unroll
        for (int j = 0; j < 4; j++)
#pragma unroll
            for (int q = 0; q < 4; q++) c[i][j][q] = 0.f;

    int nk = Ktot >> 6;
    stage_load(sbase, 0, Ah, Al, Bh, Bl, row0, col0, 0, Ktot, tid);
    CP_COMMIT();

    for (int it = 0; it < nk; it++) {
        if (it + 1 < nk) {
            stage_load(sbase, (it + 1) & 1, Ah, Al, Bh, Bl, row0, col0,
                       (it + 1) << 6, Ktot, tid);
            CP_COMMIT();
            CP_WAIT1();
        } else {
            CP_WAIT0();
        }
        __syncthreads();

        unsigned stb = sbase + (unsigned)((it & 1) * STG_B);

#pragma unroll
        for (int ks = 0; ks < 4; ks++) {
            int kc = ks * 16;
            unsigned ah[2][4], al[2][4], bh[2][4], bl[2][4];
#pragma unroll
            for (int ma = 0; ma < 2; ma++) {
                int el = (wm * 32 + ma * 16 + (lane & 15)) * PADK
                       + kc + ((lane >> 4) << 3);
                LDSM4(ah[ma], stb + OFF_AH + el * 2);
                LDSM4(al[ma], stb + OFF_AL + el * 2);
            }
#pragma unroll
            for (int nb = 0; nb < 2; nb++) {
                int n = wn * 32 + nb * 16 + ((lane >> 4) << 3) + (lane & 7);
                int el = n * PADK + kc + (((lane >> 3) & 1) << 3);
                LDSM4(bh[nb], stb + OFF_BH + el * 2);
                LDSM4(bl[nb], stb + OFF_BL + el * 2);
            }
#pragma unroll
            for (int ma = 0; ma < 2; ma++)
#pragma unroll
                for (int na = 0; na < 4; na++) {
                    const unsigned* bph = &bh[na >> 1][(na & 1) * 2];
                    const unsigned* bpl = &bl[na >> 1][(na & 1) * 2];
                    MMA16816(c[ma][na], ah[ma], bph);
                    MMA16816(c[ma][na], ah[ma], bpl);
                    MMA16816(c[ma][na], al[ma], bph);
                }
        }
        __syncthreads();
    }

#pragma unroll
    for (int ma = 0; ma < 2; ma++) {
        int r0 = row0 + wm * 32 + ma * 16 + (lane >> 2);
#pragma unroll
        for (int na = 0; na < 4; na++) {
            int col = col0 + wn * 32 + na * 8 + ((lane & 3) << 1);
            emit2(r0,     col, make_float2(c[ma][na][0], c[ma][na][1]),
                  bias, relu, Cf, Ch, Cl, Nld);
            emit2(r0 + 8, col, make_float2(c[ma][na][2], c[ma][na][3]),
                  bias, relu, Cf, Ch, Cl, Nld);
        }
    }
}

/* ------------------ fused GATv2 softmax-aggregation (layer 1) ----------- */
__device__ __forceinline__ float lrelu(float x) { return x > 0.f ? x : NEG * x; }

__global__ void gat_agg1(const float* __restrict__ xlr, const float* __restrict__ att,
                         const float* __restrict__ bias,
                         bf16* __restrict__ oh, bf16* __restrict__ ol)
{
    const int HEADS = 4, D = 1024;
    int w = (blockIdx.x * blockDim.x + threadIdx.x) >> 5;
    int lane = threadIdx.x & 31;
    if (w >= N_NODES * HEADS) return;
    int dst = w / HEADS;
    int h   = w - dst * HEADS;
    int cb = h * HID + lane * 4;

    const float* xl = xlr;
    const float* xr = xlr + 512;
    float4 a4 = *(const float4*)(att + h * HID + lane * 4);
    float4 r4 = *(const float4*)(xr + (size_t)dst * D + cb);

    float m = -1e30f, s = 0.f;
    float4 acc = make_float4(0.f, 0.f, 0.f, 0.f);

    int j = g_off[dst], end = g_off[dst + 1];
    for (; j < end; j++) {
        int src = g_srcs[j];
        float4 l4 = *(const float4*)(xl + (size_t)src * D + cb);
        float p = lrelu(l4.x + r4.x) * a4.x;
        p      += lrelu(l4.y + r4.y) * a4.y;
        p      += lrelu(l4.z + r4.z) * a4.z;
        p      += lrelu(l4.w + r4.w) * a4.w;
#pragma unroll
        for (int o = 16; o > 0; o >>= 1) p += __shfl_xor_sync(0xffffffffu, p, o);
        float mn = fmaxf(m, p);
        float cc = __expf(m - mn);
        float wg = __expf(p - mn);
        s = s * cc + wg;
        acc.x = acc.x * cc + wg * l4.x;
        acc.y = acc.y * cc + wg * l4.y;
        acc.z = acc.z * cc + wg * l4.z;
        acc.w = acc.w * cc + wg * l4.w;
        m = mn;
    }
    float inv = 1.f / (s + 1e-16f);
    float4 bb = *(const float4*)(bias + h * HID + lane * 4);
    float4 o4;
    o4.x = fmaxf(acc.x * inv + bb.x, 0.f);
    o4.y = fmaxf(acc.y * inv + bb.y, 0.f);
    o4.z = fmaxf(acc.z * inv + bb.z, 0.f);
    o4.w = fmaxf(acc.w * inv + bb.w, 0.f);
    split_store4(oh, ol, (size_t)dst * 512 + cb, o4);
}

/* -------- layer-2 aggregation fused with output projection -------------- */
__global__ void gat_out(const float* __restrict__ xlr, const float* __restrict__ att,
                        const float* __restrict__ bias,
                        const float* __restrict__ W, const float* __restrict__ ob,
                        float* __restrict__ y)
{
    const int D = 256;
    __shared__ float Ws[HID * 10];
    __shared__ float bs[10];
    for (int i = threadIdx.x; i < HID * 10; i += blockDim.x) Ws[i] = W[i];
    if (threadIdx.x < 10) bs[threadIdx.x] = ob[threadIdx.x];
    __syncthreads();

    int w = (blockIdx.x * blockDim.x + threadIdx.x) >> 5;
    int lane = threadIdx.x & 31;
    if (w >= N_NODES) return;
    int dst = w;
    int cb = lane * 4;

    const float* xl = xlr;
    const float* xr = xlr + 128;
    float4 a4 = *(const float4*)(att + cb);
    float4 r4 = *(const float4*)(xr + (size_t)dst * D + cb);

    float m = -1e30f, s = 0.f;
    float4 acc = make_float4(0.f, 0.f, 0.f, 0.f);

    int j = g_off[dst], end = g_off[dst + 1];
    for (; j < end; j++) {
        int src = g_srcs[j];
        float4 l4 = *(const float4*)(xl + (size_t)src * D + cb);
        float p = lrelu(l4.x + r4.x) * a4.x;
        p      += lrelu(l4.y + r4.y) * a4.y;
        p      += lrelu(l4.z + r4.z) * a4.z;
        p      += lrelu(l4.w + r4.w) * a4.w;
#pragma unroll
        for (int o = 16; o > 0; o >>= 1) p += __shfl_xor_sync(0xffffffffu, p, o);
        float mn = fmaxf(m, p);
        float cc = __expf(m - mn);
        float wg = __expf(p - mn);
        s = s * cc + wg;
        acc.x = acc.x * cc + wg * l4.x;
        acc.y = acc.y * cc + wg * l4.y;
        acc.z = acc.z * cc + wg * l4.z;
        acc.w = acc.w * cc + wg * l4.w;
        m = mn;
    }
    float inv = 1.f / (s + 1e-16f);
    float4 bb = *(const float4*)(bias + cb);
    float4 o4;
    o4.x = acc.x * inv + bb.x;
    o4.y = acc.y * inv + bb.y;
    o4.z = acc.z * inv + bb.z;
    o4.w = acc.w * inv + bb.w;

    /* fused [128] @ [128,10] */
    int k = lane * 4;
    float p[10];
#pragma unroll
    for (int o = 0; o < 10; o++)
        p[o] = o4.x * Ws[(k + 0) * 10 + o] + o4.y * Ws[(k + 1) * 10 + o] +
               o4.z * Ws[(k + 2) * 10 + o] + o4.w * Ws[(k + 3) * 10 + o];
#pragma unroll
    for (int o = 0; o < 10; o++)
#pragma unroll
        for (int off = 16; off > 0; off >>= 1)
            p[o] += __shfl_xor_sync(0xffffffffu, p[o], off);
    if (lane < 10) y[(size_t)dst * 10 + lane] = p[lane] + bs[lane];
}

/* ------------------ launch ---------------------------------------------- */
extern "C" void kernel_launch(void* const* d_in, const int* in_sizes, int n_in,
                              void* d_out, int out_size)
{
    const float* x_player   = (const float*)d_in[0];
    const int*   edge_index = (const int*)  d_in[1];
    const float* emb        = (const float*)d_in[2];
    const float* proj_W     = (const float*)d_in[3];
    const float* proj_b     = (const float*)d_in[4];
    const float* W1l        = (const float*)d_in[5];
    const float* W1r        = (const float*)d_in[6];
    const float* att1       = (const float*)d_in[7];
    const float* b1         = (const float*)d_in[8];
    const float* W2l        = (const float*)d_in[9];
    const float* W2r        = (const float*)d_in[10];
    const float* att2       = (const float*)d_in[11];
    const float* b2         = (const float*)d_in[12];
    const float* out_W      = (const float*)d_in[13];
    const float* out_b      = (const float*)d_in[14];
    float* y = (float*)d_out;

    bf16 *xinh, *xinl, *x0h, *x0l, *x1h, *x1l;
    bf16 *pWh, *pWl, *W1h, *W1lo, *W2h, *W2lo;
    float *xlr1, *xlr2;
    cudaGetSymbolAddress((void**)&xinh, g_xinh); cudaGetSymbolAddress((void**)&xinl, g_xinl);
    cudaGetSymbolAddress((void**)&x0h,  g_x0h);  cudaGetSymbolAddress((void**)&x0l,  g_x0l);
    cudaGetSymbolAddress((void**)&x1h,  g_x1h);  cudaGetSymbolAddress((void**)&x1l,  g_x1l);
    cudaGetSymbolAddress((void**)&xlr1, g_xlr1); cudaGetSymbolAddress((void**)&xlr2, g_xlr2);
    cudaGetSymbolAddress((void**)&pWh,  g_pWh);  cudaGetSymbolAddress((void**)&pWl,  g_pWl);
    cudaGetSymbolAddress((void**)&W1h,  g_W1h);  cudaGetSymbolAddress((void**)&W1lo, g_W1l);
    cudaGetSymbolAddress((void**)&W2h,  g_W2h);  cudaGetSymbolAddress((void**)&W2lo, g_W2l);

    cudaFuncSetAttribute(mm_bf16, cudaFuncAttributeMaxDynamicSharedMemorySize, SM_SZ);

    /* CSR build (self-loops placed in k_scan) */
    k_init_deg<<<(N_NODES + 255) / 256, 256>>>();
    k_count   <<<(N_EDGES + 255) / 256, 256>>>(edge_index);
    k_scan    <<<1, 1024>>>();
    k_scatter <<<(N_EDGES + 255) / 256, 256>>>(edge_index);

    /* gather + weight conversions (merged l|r buffers) */
    k_gather<<<(N_NODES * KIN + 255) / 256, 256>>>(x_player, emb);
    k_convw<<<(KIN * HID + 255) / 256, 256>>>(proj_W, pWh, pWl, KIN, HID);
    k_convw<<<(HID * 512 + 255) / 256, 256>>>(W1l, W1h,             W1lo,             HID, 512);
    k_convw<<<(HID * 512 + 255) / 256, 256>>>(W1r, W1h + 512 * HID, W1lo + 512 * HID, HID, 512);
    k_convw<<<(512 * HID + 255) / 256, 256>>>(W2l, W2h,             W2lo,             512, HID);
    k_convw<<<(512 * HID + 255) / 256, 256>>>(W2r, W2h + 128 * 512, W2lo + 128 * 512, 512, HID);

    /* proj: [MPAD,192]@[192,128] + b, relu, split-output */
    mm_bf16<<<dim3(1, MPAD / 64), 256, SM_SZ>>>(
        xinh, xinl, pWh, pWl, proj_b, nullptr, x0h, x0l, KIN, HID, 1);

    /* GAT layer 1 linear: one merged GEMM N=1024 -> [xl|xr] rows */
    mm_bf16<<<dim3(8, MPAD / 64), 256, SM_SZ>>>(
        x0h, x0l, W1h, W1lo, nullptr, xlr1, nullptr, nullptr, HID, 1024, 0);
    gat_agg1<<<(N_NODES * 4 * 32 + 255) / 256, 256>>>(xlr1, att1, b1, x1h, x1l);

    /* GAT layer 2 linear: merged GEMM N=256 */
    mm_bf16<<<dim3(2, MPAD / 64), 256, SM_SZ>>>(
        x1h, x1l, W2h, W2lo, nullptr, xlr2, nullptr, nullptr, 512, 256, 0);

    /* layer-2 aggregation fused with output projection */
    gat_out<<<(N_NODES * 32 + 255) / 256, 256>>>(xlr2, att2, b2, out_W, out_b, y);
}

// round 11
// speedup vs baseline: 1.8720x; 1.0429x over previous
#include <cuda_runtime.h>
#include <cuda_bf16.h>
#include <stdint.h>
#include <math.h>

#define N_NODES 20000
#define MPAD    20096          /* 157 * 128, also /64 = 314 */
#define N_EDGES 320000
#define ETOT    (N_EDGES + N_NODES)
#define FEAT    64
#define HID     128
#define KIN     (HID + FEAT)   /* 192 */
#define NEG     0.2f

typedef __nv_bfloat16 bf16;

/* ------------------ scratch (device globals) ----------------------------- */
__device__ __align__(256) bf16  g_xinh[MPAD * KIN];
__device__ __align__(256) bf16  g_xinl[MPAD * KIN];
__device__ __align__(256) bf16  g_x0h [MPAD * HID];
__device__ __align__(256) bf16  g_x0l [MPAD * HID];
__device__ __align__(256) float g_xlr1[MPAD * 1024];     /* [xl1(512)|xr1(512)] */
__device__ __align__(256) bf16  g_x1h [MPAD * 4 * HID];
__device__ __align__(256) bf16  g_x1l [MPAD * 4 * HID];
__device__ __align__(256) float g_xlr2[MPAD * 256];      /* [xl2(128)|xr2(128)] */
/* merged transposed split weights: [N,K] K-major */
__device__ __align__(256) bf16  g_pWh [HID * KIN],   g_pWl [HID * KIN];
__device__ __align__(256) bf16  g_W1h [1024 * HID],  g_W1l [1024 * HID];
__device__ __align__(256) bf16  g_W2h [256 * 4 * HID], g_W2l [256 * 4 * HID];
__device__ int   g_deg[N_NODES];    /* invariant: all-zero at launch entry */
__device__ int   g_off[N_NODES + 1];
__device__ int   g_cur[N_NODES];
__device__ int   g_srcs[ETOT];

/* ------------------ pack helpers ---------------------------------------- */
__device__ __forceinline__ unsigned int pack2(float a, float b) {
    union { __nv_bfloat162 v; unsigned int u; } c;
    c.v = __nv_bfloat162(__float2bfloat16(a), __float2bfloat16(b));
    return c.u;
}
__device__ __forceinline__ void split_store4(bf16* hp, bf16* lp, size_t o, float4 v) {
    bf16 hx = __float2bfloat16(v.x), hy = __float2bfloat16(v.y);
    bf16 hz = __float2bfloat16(v.z), hw = __float2bfloat16(v.w);
    union { __nv_bfloat162 v; unsigned int u; } a, b;
    a.v = __nv_bfloat162(hx, hy); b.v = __nv_bfloat162(hz, hw);
    *(uint2*)(hp + o) = make_uint2(a.u, b.u);
    *(uint2*)(lp + o) = make_uint2(
        pack2(v.x - __bfloat162float(hx), v.y - __bfloat162float(hy)),
        pack2(v.z - __bfloat162float(hz), v.w - __bfloat162float(hw)));
}
__device__ __forceinline__ void split_store(bf16* h, bf16* l, size_t idx, float v) {
    bf16 hb = __float2bfloat16(v);
    h[idx] = hb;
    l[idx] = __float2bfloat16(v - __bfloat162float(hb));
}

/* ------------------ PTX helpers (baseline sm_80+) ------------------------ */
__device__ __forceinline__ unsigned int smem_u32(const void* p) {
    unsigned int a;
    asm("{ .reg .u64 t; cvta.to.shared.u64 t, %1; cvt.u32.u64 %0, t; }" : "=r"(a) : "l"(p));
    return a;
}
#define CP16(dst, src)  asm volatile("cp.async.cg.shared.global [%0], [%1], 16;" :: "r"(dst), "l"(src) : "memory")
#define CP_COMMIT()     asm volatile("cp.async.commit_group;" ::: "memory")
#define CP_WAIT1()      asm volatile("cp.async.wait_group 1;" ::: "memory")
#define CP_WAIT0()      asm volatile("cp.async.wait_group 0;" ::: "memory")

#define LDSM4(d, addr) \
    asm volatile("ldmatrix.sync.aligned.m8n8.x4.shared.b16 {%0,%1,%2,%3}, [%4];" \
        : "=r"((d)[0]), "=r"((d)[1]), "=r"((d)[2]), "=r"((d)[3]) : "r"(addr))

#define MMA16816(c, a, b) \
    asm volatile("mma.sync.aligned.m16n8k16.row.col.f32.bf16.bf16.f32 " \
        "{%0,%1,%2,%3}, {%4,%5,%6,%7}, {%8,%9}, {%0,%1,%2,%3};" \
        : "+f"((c)[0]), "+f"((c)[1]), "+f"((c)[2]), "+f"((c)[3]) \
        : "r"((a)[0]), "r"((a)[1]), "r"((a)[2]), "r"((a)[3]), \
          "r"((b)[0]), "r"((b)[1]))

/* ------------------ CSR build ------------------------------------------- */
__global__ void k_count(const int* __restrict__ ei) {
    int e = blockIdx.x * blockDim.x + threadIdx.x;
    if (e < N_EDGES) atomicAdd(&g_deg[ei[N_EDGES + e]], 1);
}
/* scan (deg+1 for self loop), place self-loop at segment head.
 * ALSO resets g_deg to 0 for the next kernel_launch invocation (the harness
 * replays the whole launch; device globals persist across replays). */
__global__ void k_scan() {
    __shared__ int ps[1024];
    int t = threadIdx.x;
    const int CH = (N_NODES + 1023) / 1024;
    int base = t * CH, s = 0;
    for (int i = 0; i < CH; i++) { int idx = base + i; if (idx < N_NODES) s += g_deg[idx] + 1; }
    ps[t] = s;
    __syncthreads();
    for (int off = 1; off < 1024; off <<= 1) {
        int v = (t >= off) ? ps[t - off] : 0;
        __syncthreads();
        ps[t] += v;
        __syncthreads();
    }
    int run = ps[t] - s;
    for (int i = 0; i < CH; i++) {
        int idx = base + i;
        if (idx < N_NODES) {
            int d = g_deg[idx];
            g_deg[idx] = 0;                   /* restore invariant for next call */
            g_off[idx] = run;
            g_srcs[run] = idx;                /* self loop first */
            g_cur[idx] = run + 1;
            run += d + 1;
        }
    }
    if (t == 1023) g_off[N_NODES] = ps[1023];
}
__global__ void k_scatter(const int* __restrict__ ei) {
    int e = blockIdx.x * blockDim.x + threadIdx.x;
    if (e < N_EDGES) {
        int d = ei[N_EDGES + e];
        int p = atomicAdd(&g_cur[d], 1);
        g_srcs[p] = ei[e];
    }
}

/* ------------------ merged prep: gather + all weight conversions --------- */
#define PREP_G   (N_NODES * KIN)          /* 3,840,000 */
#define PREP_PW  (KIN * HID)              /* 24,576 */
#define PREP_W1  (HID * 512)              /* 65,536 (x2) */
#define PREP_W2  (512 * HID)              /* 65,536 (x2) */
#define PREP_TOT (PREP_G + PREP_PW + 2 * PREP_W1 + 2 * PREP_W2)

__device__ __forceinline__ void conv_one(const float* __restrict__ W,
                                         bf16* h, bf16* l, int K, int N, int idx) {
    int k = idx / N, n = idx - k * N;
    split_store(h, l, (size_t)n * K + k, W[(size_t)k * N + n]);
}

__global__ void k_prep(const float* __restrict__ xp, const float* __restrict__ emb,
                       const float* __restrict__ proj_W,
                       const float* __restrict__ W1l, const float* __restrict__ W1r,
                       const float* __restrict__ W2l, const float* __restrict__ W2r)
{
    int idx = blockIdx.x * blockDim.x + threadIdx.x;
    if (idx < PREP_G) {
        int i = idx / KIN, k = idx - i * KIN;
        float v;
        if (k < HID) {
            int id = (int)xp[i * (FEAT + 1)];
            v = emb[id * HID + k];
        } else {
            v = xp[i * (FEAT + 1) + 1 + (k - HID)];
        }
        split_store(g_xinh, g_xinl, (size_t)i * KIN + k, v);
        return;
    }
    idx -= PREP_G;
    if (idx < PREP_PW) { conv_one(proj_W, g_pWh, g_pWl, KIN, HID, idx); return; }
    idx -= PREP_PW;
    if (idx < PREP_W1) { conv_one(W1l, g_W1h, g_W1l, HID, 512, idx); return; }
    idx -= PREP_W1;
    if (idx < PREP_W1) { conv_one(W1r, g_W1h + 512 * HID, g_W1l + 512 * HID, HID, 512, idx); return; }
    idx -= PREP_W1;
    if (idx < PREP_W2) { conv_one(W2l, g_W2h, g_W2l, 512, HID, idx); return; }
    idx -= PREP_W2;
    if (idx < PREP_W2) { conv_one(W2r, g_W2h + 128 * 512, g_W2l + 128 * 512, 512, HID, idx); return; }
}

/* ------------------ HMMA split-bf16 GEMM --------------------------------- */
/* CTA 64x128, BK=64, 8 warps (2M x 4N), warp tile 32x32, occ 2.             */
#define PADK    72
#define A_EL    (64 * PADK)
#define B_EL    (128 * PADK)
#define OFF_AH  0
#define OFF_AL  (A_EL * 2)
#define OFF_BH  (2 * A_EL * 2)
#define OFF_BL  (2 * A_EL * 2 + B_EL * 2)
#define STG_B   ((2 * A_EL + 2 * B_EL) * 2)   /* 55296 bytes */
#define SM_SZ   (2 * STG_B)                   /* 110592 bytes */

__device__ __forceinline__ void stage_load(
    unsigned sbase, int s,
    const bf16* __restrict__ Ah, const bf16* __restrict__ Al,
    const bf16* __restrict__ Bh, const bf16* __restrict__ Bl,
    int row0, int col0, int k0, int Ktot, int tid)
{
    unsigned stb = sbase + (unsigned)(s * STG_B);
#pragma unroll
    for (int q = 0; q < 2; q++) {
        int idx = tid + 256 * q;
        int r = idx >> 3, cc = idx & 7;
        unsigned so = (unsigned)((r * PADK + cc * 8) * 2);
        size_t ga = (size_t)(row0 + r) * Ktot + k0 + cc * 8;
        CP16(stb + OFF_AH + so, Ah + ga);
        CP16(stb + OFF_AL + so, Al + ga);
    }
#pragma unroll
    for (int q = 0; q < 4; q++) {
        int idx = tid + 256 * q;
        int r = idx >> 3, cc = idx & 7;
        unsigned so = (unsigned)((r * PADK + cc * 8) * 2);
        size_t gb = (size_t)(col0 + r) * Ktot + k0 + cc * 8;
        CP16(stb + OFF_BH + so, Bh + gb);
        CP16(stb + OFF_BL + so, Bl + gb);
    }
}

__device__ __forceinline__ void emit2(int r, int col, float2 v,
                                      const float* __restrict__ bias, int relu,
                                      float* __restrict__ Cf, bf16* __restrict__ Ch,
                                      bf16* __restrict__ Cl, int Nld)
{
    if (bias) { v.x += bias[col]; v.y += bias[col + 1]; }
    if (relu) { v.x = fmaxf(v.x, 0.f); v.y = fmaxf(v.y, 0.f); }
    size_t o = (size_t)r * Nld + col;
    if (Cf) {
        *(float2*)(Cf + o) = v;
    } else {
        bf16 hx = __float2bfloat16(v.x), hy = __float2bfloat16(v.y);
        union { __nv_bfloat162 b; unsigned u; } H;
        H.b = __nv_bfloat162(hx, hy);
        *(unsigned*)(Ch + o) = H.u;
        *(unsigned*)(Cl + o) = pack2(v.x - __bfloat162float(hx),
                                     v.y - __bfloat162float(hy));
    }
}

__global__ __launch_bounds__(256, 2)
void mm_bf16(const bf16* __restrict__ Ah, const bf16* __restrict__ Al,
             const bf16* __restrict__ Bh, const bf16* __restrict__ Bl,
             const float* __restrict__ bias,
             float* __restrict__ Cf, bf16* __restrict__ Ch, bf16* __restrict__ Cl,
             int Ktot, int Nld, int relu)
{
    extern __shared__ char smem[];
    unsigned sbase = smem_u32(smem);
    int tid = threadIdx.x;
    int lane = tid & 31, wrp = tid >> 5;
    int wm = wrp & 1, wn = wrp >> 1;
    int row0 = blockIdx.y * 64, col0 = blockIdx.x * 128;

    float c[2][4][4];
#pragma unroll
    for (int i = 0; i < 2; i++)
#pragma unroll
        for (int j = 0; j < 4; j++)
#pragma unroll
            for (int q = 0; q < 4; q++) c[i][j][q] = 0.f;

    int nk = Ktot >> 6;
    stage_load(sbase, 0, Ah, Al, Bh, Bl, row0, col0, 0, Ktot, tid);
    CP_COMMIT();

    for (int it = 0; it < nk; it++) {
        if (it + 1 < nk) {
            stage_load(sbase, (it + 1) & 1, Ah, Al, Bh, Bl, row0, col0,
                       (it + 1) << 6, Ktot, tid);
            CP_COMMIT();
            CP_WAIT1();
        } else {
            CP_WAIT0();
        }
        __syncthreads();

        unsigned stb = sbase + (unsigned)((it & 1) * STG_B);

#pragma unroll
        for (int ks = 0; ks < 4; ks++) {
            int kc = ks * 16;
            unsigned ah[2][4], al[2][4], bh[2][4], bl[2][4];
#pragma unroll
            for (int ma = 0; ma < 2; ma++) {
                int el = (wm * 32 + ma * 16 + (lane & 15)) * PADK
                       + kc + ((lane >> 4) << 3);
                LDSM4(ah[ma], stb + OFF_AH + el * 2);
                LDSM4(al[ma], stb + OFF_AL + el * 2);
            }
#pragma unroll
            for (int nb = 0; nb < 2; nb++) {
                int n = wn * 32 + nb * 16 + ((lane >> 4) << 3) + (lane & 7);
                int el = n * PADK + kc + (((lane >> 3) & 1) << 3);
                LDSM4(bh[nb], stb + OFF_BH + el * 2);
                LDSM4(bl[nb], stb + OFF_BL + el * 2);
            }
#pragma unroll
            for (int ma = 0; ma < 2; ma++)
#pragma unroll
                for (int na = 0; na < 4; na++) {
                    const unsigned* bph = &bh[na >> 1][(na & 1) * 2];
                    const unsigned* bpl = &bl[na >> 1][(na & 1) * 2];
                    MMA16816(c[ma][na], ah[ma], bph);
                    MMA16816(c[ma][na], ah[ma], bpl);
                    MMA16816(c[ma][na], al[ma], bph);
                }
        }
        __syncthreads();
    }

#pragma unroll
    for (int ma = 0; ma < 2; ma++) {
        int r0 = row0 + wm * 32 + ma * 16 + (lane >> 2);
#pragma unroll
        for (int na = 0; na < 4; na++) {
            int col = col0 + wn * 32 + na * 8 + ((lane & 3) << 1);
            emit2(r0,     col, make_float2(c[ma][na][0], c[ma][na][1]),
                  bias, relu, Cf, Ch, Cl, Nld);
            emit2(r0 + 8, col, make_float2(c[ma][na][2], c[ma][na][3]),
                  bias, relu, Cf, Ch, Cl, Nld);
        }
    }
}

/* ------------------ GATv2 aggregation helpers ---------------------------- */
__device__ __forceinline__ float lrelu(float x) { return x > 0.f ? x : NEG * x; }

struct OSM { float m, s; float4 acc; };
__device__ __forceinline__ void osm_init(OSM& o) {
    o.m = -1e30f; o.s = 0.f; o.acc = make_float4(0.f, 0.f, 0.f, 0.f);
}
__device__ __forceinline__ void osm_step(OSM& o, float4 l4, float4 r4, float4 a4) {
    float p = lrelu(l4.x + r4.x) * a4.x;
    p      += lrelu(l4.y + r4.y) * a4.y;
    p      += lrelu(l4.z + r4.z) * a4.z;
    p      += lrelu(l4.w + r4.w) * a4.w;
#pragma unroll
    for (int off = 16; off > 0; off >>= 1) p += __shfl_xor_sync(0xffffffffu, p, off);
    float mn = fmaxf(o.m, p);
    float cc = __expf(o.m - mn);
    float wg = __expf(p - mn);
    o.s = o.s * cc + wg;
    o.acc.x = o.acc.x * cc + wg * l4.x;
    o.acc.y = o.acc.y * cc + wg * l4.y;
    o.acc.z = o.acc.z * cc + wg * l4.z;
    o.acc.w = o.acc.w * cc + wg * l4.w;
    o.m = mn;
}
__device__ __forceinline__ void osm_merge(OSM& a, const OSM& b) {
    float mn = fmaxf(a.m, b.m);
    float ca = __expf(a.m - mn), cb = __expf(b.m - mn);
    a.s = a.s * ca + b.s * cb;
    a.acc.x = a.acc.x * ca + b.acc.x * cb;
    a.acc.y = a.acc.y * ca + b.acc.y * cb;
    a.acc.z = a.acc.z * ca + b.acc.z * cb;
    a.acc.w = a.acc.w * ca + b.acc.w * cb;
    a.m = mn;
}

/* ------------------ layer-1 aggregation ---------------------------------- */
__global__ void gat_agg1(const float* __restrict__ xlr, const float* __restrict__ att,
                         const float* __restrict__ bias,
                         bf16* __restrict__ oh, bf16* __restrict__ ol)
{
    const int HEADS = 4, D = 1024;
    int w = (blockIdx.x * blockDim.x + threadIdx.x) >> 5;
    int lane = threadIdx.x & 31;
    if (w >= N_NODES * HEADS) return;
    int dst = w / HEADS;
    int h   = w - dst * HEADS;
    int cb = h * HID + lane * 4;

    const float* xl = xlr;
    const float* xr = xlr + 512;
    float4 a4 = *(const float4*)(att + h * HID + lane * 4);
    float4 r4 = *(const float4*)(xr + (size_t)dst * D + cb);

    OSM o0, o1;
    osm_init(o0); osm_init(o1);

    int j = g_off[dst], end = g_off[dst + 1];
    if ((end - j) & 1) {
        float4 l4 = *(const float4*)(xl + (size_t)g_srcs[j] * D + cb);
        osm_step(o0, l4, r4, a4);
        j++;
    }
    for (; j < end; j += 2) {
        int sA = g_srcs[j], sB = g_srcs[j + 1];
        float4 lA = *(const float4*)(xl + (size_t)sA * D + cb);
        float4 lB = *(const float4*)(xl + (size_t)sB * D + cb);
        osm_step(o0, lA, r4, a4);
        osm_step(o1, lB, r4, a4);
    }
    osm_merge(o0, o1);

    float inv = 1.f / (o0.s + 1e-16f);
    float4 bb = *(const float4*)(bias + h * HID + lane * 4);
    float4 o4;
    o4.x = fmaxf(o0.acc.x * inv + bb.x, 0.f);
    o4.y = fmaxf(o0.acc.y * inv + bb.y, 0.f);
    o4.z = fmaxf(o0.acc.z * inv + bb.z, 0.f);
    o4.w = fmaxf(o0.acc.w * inv + bb.w, 0.f);
    split_store4(oh, ol, (size_t)dst * 512 + cb, o4);
}

/* -------- layer-2 aggregation fused with output projection -------------- */
__global__ void gat_out(const float* __restrict__ xlr, const float* __restrict__ att,
                        const float* __restrict__ bias,
                        const float* __restrict__ W, const float* __restrict__ ob,
                        float* __restrict__ y)
{
    const int D = 256;
    __shared__ float Ws[HID * 10];
    __shared__ float bs[10];
    for (int i = threadIdx.x; i < HID * 10; i += blockDim.x) Ws[i] = W[i];
    if (threadIdx.x < 10) bs[threadIdx.x] = ob[threadIdx.x];
    __syncthreads();

    int w = (blockIdx.x * blockDim.x + threadIdx.x) >> 5;
    int lane = threadIdx.x & 31;
    if (w >= N_NODES) return;
    int dst = w;
    int cb = lane * 4;

    const float* xl = xlr;
    const float* xr = xlr + 128;
    float4 a4 = *(const float4*)(att + cb);
    float4 r4 = *(const float4*)(xr + (size_t)dst * D + cb);

    OSM o0, o1;
    osm_init(o0); osm_init(o1);

    int j = g_off[dst], end = g_off[dst + 1];
    if ((end - j) & 1) {
        float4 l4 = *(const float4*)(xl + (size_t)g_srcs[j] * D + cb);
        osm_step(o0, l4, r4, a4);
        j++;
    }
    for (; j < end; j += 2) {
        int sA = g_srcs[j], sB = g_srcs[j + 1];
        float4 lA = *(const float4*)(xl + (size_t)sA * D + cb);
        float4 lB = *(const float4*)(xl + (size_t)sB * D + cb);
        osm_step(o0, lA, r4, a4);
        osm_step(o1, lB, r4, a4);
    }
    osm_merge(o0, o1);

    float inv = 1.f / (o0.s + 1e-16f);
    float4 bb = *(const float4*)(bias + cb);
    float4 o4;
    o4.x = o0.acc.x * inv + bb.x;
    o4.y = o0.acc.y * inv + bb.y;
    o4.z = o0.acc.z * inv + bb.z;
    o4.w = o0.acc.w * inv + bb.w;

    /* fused [128] @ [128,10] */
    int k = lane * 4;
    float p[10];
#pragma unroll
    for (int o = 0; o < 10; o++)
        p[o] = o4.x * Ws[(k + 0) * 10 + o] + o4.y * Ws[(k + 1) * 10 + o] +
               o4.z * Ws[(k + 2) * 10 + o] + o4.w * Ws[(k + 3) * 10 + o];
#pragma unroll
    for (int o = 0; o < 10; o++)
#pragma unroll
        for (int off = 16; off > 0; off >>= 1)
            p[o] += __shfl_xor_sync(0xffffffffu, p[o], off);
    if (lane < 10) y[(size_t)dst * 10 + lane] = p[lane] + bs[lane];
}

/* ------------------ launch ---------------------------------------------- */
extern "C" void kernel_launch(void* const* d_in, const int* in_sizes, int n_in,
                              void* d_out, int out_size)
{
    const float* x_player   = (const float*)d_in[0];
    const int*   edge_index = (const int*)  d_in[1];
    const float* emb        = (const float*)d_in[2];
    const float* proj_W     = (const float*)d_in[3];
    const float* proj_b     = (const float*)d_in[4];
    const float* W1l        = (const float*)d_in[5];
    const float* W1r        = (const float*)d_in[6];
    const float* att1       = (const float*)d_in[7];
    const float* b1         = (const float*)d_in[8];
    const float* W2l        = (const float*)d_in[9];
    const float* W2r        = (const float*)d_in[10];
    const float* att2       = (const float*)d_in[11];
    const float* b2         = (const float*)d_in[12];
    const float* out_W      = (const float*)d_in[13];
    const float* out_b      = (const float*)d_in[14];
    float* y = (float*)d_out;

    bf16 *xinh, *xinl, *x0h, *x0l, *x1h, *x1l;
    bf16 *pWh, *pWl, *W1h, *W1lo, *W2h, *W2lo;
    float *xlr1, *xlr2;
    cudaGetSymbolAddress((void**)&xinh, g_xinh); cudaGetSymbolAddress((void**)&xinl, g_xinl);
    cudaGetSymbolAddress((void**)&x0h,  g_x0h);  cudaGetSymbolAddress((void**)&x0l,  g_x0l);
    cudaGetSymbolAddress((void**)&x1h,  g_x1h);  cudaGetSymbolAddress((void**)&x1l,  g_x1l);
    cudaGetSymbolAddress((void**)&xlr1, g_xlr1); cudaGetSymbolAddress((void**)&xlr2, g_xlr2);
    cudaGetSymbolAddress((void**)&pWh,  g_pWh);  cudaGetSymbolAddress((void**)&pWl,  g_pWl);
    cudaGetSymbolAddress((void**)&W1h,  g_W1h);  cudaGetSymbolAddress((void**)&W1lo, g_W1l);
    cudaGetSymbolAddress((void**)&W2h,  g_W2h);  cudaGetSymbolAddress((void**)&W2lo, g_W2l);

    cudaFuncSetAttribute(mm_bf16, cudaFuncAttributeMaxDynamicSharedMemorySize, SM_SZ);

    /* CSR build (deg reset inside k_scan keeps replays deterministic) */
    k_count  <<<(N_EDGES + 255) / 256, 256>>>(edge_index);
    k_scan   <<<1, 1024>>>();
    k_scatter<<<(N_EDGES + 255) / 256, 256>>>(edge_index);

    /* merged gather + weight conversions */
    k_prep<<<(PREP_TOT + 255) / 256, 256>>>(x_player, emb, proj_W, W1l, W1r, W2l, W2r);

    /* proj: [MPAD,192]@[192,128] + b, relu, split-output */
    mm_bf16<<<dim3(1, MPAD / 64), 256, SM_SZ>>>(
        xinh, xinl, pWh, pWl, proj_b, nullptr, x0h, x0l, KIN, HID, 1);

    /* GAT layer 1 linear: merged GEMM N=1024 -> [xl|xr] rows */
    mm_bf16<<<dim3(8, MPAD / 64), 256, SM_SZ>>>(
        x0h, x0l, W1h, W1lo, nullptr, xlr1, nullptr, nullptr, HID, 1024, 0);
    gat_agg1<<<(N_NODES * 4 * 32 + 255) / 256, 256>>>(xlr1, att1, b1, x1h, x1l);

    /* GAT layer 2 linear: merged GEMM N=256 */
    mm_bf16<<<dim3(2, MPAD / 64), 256, SM_SZ>>>(
        x1h, x1l, W2h, W2lo, nullptr, xlr2, nullptr, nullptr, 512, 256, 0);

    /* layer-2 aggregation fused with output projection */
    gat_out<<<(N_NODES * 32 + 255) / 256, 256>>>(xlr2, att2, b2, out_W, out_b, y);
}

// round 12
// speedup vs baseline: 1.9430x; 1.0380x over previous
#include <cuda_runtime.h>
#include <cuda_bf16.h>
#include <cuda_fp16.h>
#include <stdint.h>
#include <math.h>

#define N_NODES 20000
#define MPAD    20096          /* 157 * 128, also /64 = 314 */
#define N_EDGES 320000
#define ETOT    (N_EDGES + N_NODES)
#define FEAT    64
#define HID     128
#define KIN     (HID + FEAT)   /* 192 */
#define NEG     0.2f

typedef __nv_bfloat16 bf16;

/* ------------------ scratch (device globals) ----------------------------- */
__device__ __align__(256) bf16  g_xinh[MPAD * KIN];
__device__ __align__(256) bf16  g_xinl[MPAD * KIN];
__device__ __align__(256) bf16  g_x0h [MPAD * HID];
__device__ __align__(256) bf16  g_x0l [MPAD * HID];
__device__ __align__(256) __half g_xl1h[MPAD * 512];     /* xl1 fp16 */
__device__ __align__(256) float  g_xr1f[MPAD * 512];     /* xr1 fp32 */
__device__ __align__(256) bf16  g_x1h [MPAD * 4 * HID];
__device__ __align__(256) bf16  g_x1l [MPAD * 4 * HID];
__device__ __align__(256) __half g_xl2h[MPAD * 128];
__device__ __align__(256) float  g_xr2f[MPAD * 128];
/* merged transposed split weights: [N,K] K-major */
__device__ __align__(256) bf16  g_pWh [HID * KIN],   g_pWl [HID * KIN];
__device__ __align__(256) bf16  g_W1h [1024 * HID],  g_W1l [1024 * HID];
__device__ __align__(256) bf16  g_W2h [256 * 4 * HID], g_W2l [256 * 4 * HID];
__device__ int   g_deg[N_NODES];    /* invariant: all-zero at launch entry */
__device__ int   g_off[N_NODES + 1];
__device__ int   g_cur[N_NODES];
__device__ int   g_srcs[ETOT];

/* ------------------ pack helpers ---------------------------------------- */
__device__ __forceinline__ unsigned int pack2(float a, float b) {
    union { __nv_bfloat162 v; unsigned int u; } c;
    c.v = __nv_bfloat162(__float2bfloat16(a), __float2bfloat16(b));
    return c.u;
}
__device__ __forceinline__ void split_store4(bf16* hp, bf16* lp, size_t o, float4 v) {
    bf16 hx = __float2bfloat16(v.x), hy = __float2bfloat16(v.y);
    bf16 hz = __float2bfloat16(v.z), hw = __float2bfloat16(v.w);
    union { __nv_bfloat162 v; unsigned int u; } a, b;
    a.v = __nv_bfloat162(hx, hy); b.v = __nv_bfloat162(hz, hw);
    *(uint2*)(hp + o) = make_uint2(a.u, b.u);
    *(uint2*)(lp + o) = make_uint2(
        pack2(v.x - __bfloat162float(hx), v.y - __bfloat162float(hy)),
        pack2(v.z - __bfloat162float(hz), v.w - __bfloat162float(hw)));
}
__device__ __forceinline__ void split_store(bf16* h, bf16* l, size_t idx, float v) {
    bf16 hb = __float2bfloat16(v);
    h[idx] = hb;
    l[idx] = __float2bfloat16(v - __bfloat162float(hb));
}
/* 4 consecutive halves -> float4 (single 8B load) */
__device__ __forceinline__ float4 ldh4(const __half* p) {
    union { uint2 u; __half2 h[2]; } U;
    U.u = *(const uint2*)p;
    float2 a = __half22float2(U.h[0]), b = __half22float2(U.h[1]);
    return make_float4(a.x, a.y, b.x, b.y);
}

/* ------------------ PTX helpers (baseline sm_80+) ------------------------ */
__device__ __forceinline__ unsigned int smem_u32(const void* p) {
    unsigned int a;
    asm("{ .reg .u64 t; cvta.to.shared.u64 t, %1; cvt.u32.u64 %0, t; }" : "=r"(a) : "l"(p));
    return a;
}
#define CP16(dst, src)  asm volatile("cp.async.cg.shared.global [%0], [%1], 16;" :: "r"(dst), "l"(src) : "memory")
#define CP_COMMIT()     asm volatile("cp.async.commit_group;" ::: "memory")
#define CP_WAIT1()      asm volatile("cp.async.wait_group 1;" ::: "memory")
#define CP_WAIT0()      asm volatile("cp.async.wait_group 0;" ::: "memory")

#define LDSM4(d, addr) \
    asm volatile("ldmatrix.sync.aligned.m8n8.x4.shared.b16 {%0,%1,%2,%3}, [%4];" \
        : "=r"((d)[0]), "=r"((d)[1]), "=r"((d)[2]), "=r"((d)[3]) : "r"(addr))

#define MMA16816(c, a, b) \
    asm volatile("mma.sync.aligned.m16n8k16.row.col.f32.bf16.bf16.f32 " \
        "{%0,%1,%2,%3}, {%4,%5,%6,%7}, {%8,%9}, {%0,%1,%2,%3};" \
        : "+f"((c)[0]), "+f"((c)[1]), "+f"((c)[2]), "+f"((c)[3]) \
        : "r"((a)[0]), "r"((a)[1]), "r"((a)[2]), "r"((a)[3]), \
          "r"((b)[0]), "r"((b)[1]))

/* ------------------ CSR scan + scatter ----------------------------------- */
/* counting is folded into k_prep; scan resets g_deg for the next replay */
__global__ void k_scan() {
    __shared__ int ps[1024];
    int t = threadIdx.x;
    const int CH = (N_NODES + 1023) / 1024;
    int base = t * CH, s = 0;
    for (int i = 0; i < CH; i++) { int idx = base + i; if (idx < N_NODES) s += g_deg[idx] + 1; }
    ps[t] = s;
    __syncthreads();
    for (int off = 1; off < 1024; off <<= 1) {
        int v = (t >= off) ? ps[t - off] : 0;
        __syncthreads();
        ps[t] += v;
        __syncthreads();
    }
    int run = ps[t] - s;
    for (int i = 0; i < CH; i++) {
        int idx = base + i;
        if (idx < N_NODES) {
            int d = g_deg[idx];
            g_deg[idx] = 0;                   /* restore invariant for next call */
            g_off[idx] = run;
            g_srcs[run] = idx;                /* self loop first */
            g_cur[idx] = run + 1;
            run += d + 1;
        }
    }
    if (t == 1023) g_off[N_NODES] = ps[1023];
}
__global__ void k_scatter(const int* __restrict__ ei) {
    int e = blockIdx.x * blockDim.x + threadIdx.x;
    if (e < N_EDGES) {
        int d = ei[N_EDGES + e];
        int p = atomicAdd(&g_cur[d], 1);
        g_srcs[p] = ei[e];
    }
}

/* ------------------ merged prep: edge count + gather + weight conv ------- */
#define PREP_C   N_EDGES                      /* 320,000  : degree count */
#define PREP_G   (N_NODES * KIN / 4)          /* 960,000  : gather, 4-wide */
#define PREP_PW  (KIN * HID)                  /* 24,576 */
#define PREP_W1  (HID * 512)                  /* 65,536 (x2) */
#define PREP_W2  (512 * HID)                  /* 65,536 (x2) */
#define PREP_TOT (PREP_C + PREP_G + PREP_PW + 2 * PREP_W1 + 2 * PREP_W2)

__device__ __forceinline__ void conv_one(const float* __restrict__ W,
                                         bf16* h, bf16* l, int K, int N, int idx) {
    int k = idx / N, n = idx - k * N;
    split_store(h, l, (size_t)n * K + k, W[(size_t)k * N + n]);
}

__global__ void k_prep(const int* __restrict__ ei,
                       const float* __restrict__ xp, const float* __restrict__ emb,
                       const float* __restrict__ proj_W,
                       const float* __restrict__ W1l, const float* __restrict__ W1r,
                       const float* __restrict__ W2l, const float* __restrict__ W2r)
{
    int idx = blockIdx.x * blockDim.x + threadIdx.x;
    if (idx < PREP_C) {
        atomicAdd(&g_deg[ei[N_EDGES + idx]], 1);
        return;
    }
    idx -= PREP_C;
    if (idx < PREP_G) {
        int i = idx / (KIN / 4), q = idx - i * (KIN / 4);
        int k = q * 4;
        float4 v;
        if (k < HID) {
            int id = (int)xp[i * (FEAT + 1)];
            v = *(const float4*)(emb + (size_t)id * HID + k);
        } else {
            const float* f = xp + i * (FEAT + 1) + 1 + (k - HID);
            v = make_float4(f[0], f[1], f[2], f[3]);
        }
        split_store4(g_xinh, g_xinl, (size_t)i * KIN + k, v);
        return;
    }
    idx -= PREP_G;
    if (idx < PREP_PW) { conv_one(proj_W, g_pWh, g_pWl, KIN, HID, idx); return; }
    idx -= PREP_PW;
    if (idx < PREP_W1) { conv_one(W1l, g_W1h, g_W1l, HID, 512, idx); return; }
    idx -= PREP_W1;
    if (idx < PREP_W1) { conv_one(W1r, g_W1h + 512 * HID, g_W1l + 512 * HID, HID, 512, idx); return; }
    idx -= PREP_W1;
    if (idx < PREP_W2) { conv_one(W2l, g_W2h, g_W2l, 512, HID, idx); return; }
    idx -= PREP_W2;
    if (idx < PREP_W2) { conv_one(W2r, g_W2h + 128 * 512, g_W2l + 128 * 512, 512, HID, idx); return; }
}

/* ------------------ HMMA split-bf16 GEMM --------------------------------- */
/* CTA 64x128, BK=64, 8 warps (2M x 4N), warp tile 32x32, occ 2.             */
#define PADK    72
#define A_EL    (64 * PADK)
#define B_EL    (128 * PADK)
#define OFF_AH  0
#define OFF_AL  (A_EL * 2)
#define OFF_BH  (2 * A_EL * 2)
#define OFF_BL  (2 * A_EL * 2 + B_EL * 2)
#define STG_B   ((2 * A_EL + 2 * B_EL) * 2)   /* 55296 bytes */
#define SM_SZ   (2 * STG_B)                   /* 110592 bytes */

__device__ __forceinline__ void stage_load(
    unsigned sbase, int s,
    const bf16* __restrict__ Ah, const bf16* __restrict__ Al,
    const bf16* __restrict__ Bh, const bf16* __restrict__ Bl,
    int row0, int col0, int k0, int Ktot, int tid)
{
    unsigned stb = sbase + (unsigned)(s * STG_B);
#pragma unroll
    for (int q = 0; q < 2; q++) {
        int idx = tid + 256 * q;
        int r = idx >> 3, cc = idx & 7;
        unsigned so = (unsigned)((r * PADK + cc * 8) * 2);
        size_t ga = (size_t)(row0 + r) * Ktot + k0 + cc * 8;
        CP16(stb + OFF_AH + so, Ah + ga);
        CP16(stb + OFF_AL + so, Al + ga);
    }
#pragma unroll
    for (int q = 0; q < 4; q++) {
        int idx = tid + 256 * q;
        int r = idx >> 3, cc = idx & 7;
        unsigned so = (unsigned)((r * PADK + cc * 8) * 2);
        size_t gb = (size_t)(col0 + r) * Ktot + k0 + cc * 8;
        CP16(stb + OFF_BH + so, Bh + gb);
        CP16(stb + OFF_BL + so, Bl + gb);
    }
}

/* epilogue:
 *  - Ch/Cl set         -> split-bf16 output, row stride Nld
 *  - else Hx/Fx set    -> cols [0,Nsplit) as fp16 to Hx (stride Nsplit),
 *                         cols [Nsplit,2*Nsplit) as fp32 to Fx (stride Nsplit)
 */
__device__ __forceinline__ void emit2(int r, int col, float2 v,
                                      const float* __restrict__ bias, int relu,
                                      bf16* __restrict__ Ch, bf16* __restrict__ Cl,
                                      __half* __restrict__ Hx, float* __restrict__ Fx,
                                      int Nsplit, int Nld)
{
    if (bias) { v.x += bias[col]; v.y += bias[col + 1]; }
    if (relu) { v.x = fmaxf(v.x, 0.f); v.y = fmaxf(v.y, 0.f); }
    if (Ch) {
        size_t o = (size_t)r * Nld + col;
        bf16 hx = __float2bfloat16(v.x), hy = __float2bfloat16(v.y);
        union { __nv_bfloat162 b; unsigned u; } H;
        H.b = __nv_bfloat162(hx, hy);
        *(unsigned*)(Ch + o) = H.u;
        *(unsigned*)(Cl + o) = pack2(v.x - __bfloat162float(hx),
                                     v.y - __bfloat162float(hy));
    } else if (col < Nsplit) {
        *(__half2*)(Hx + (size_t)r * Nsplit + col) = __floats2half2_rn(v.x, v.y);
    } else {
        *(float2*)(Fx + (size_t)r * Nsplit + (col - Nsplit)) = v;
    }
}

__global__ __launch_bounds__(256, 2)
void mm_bf16(const bf16* __restrict__ Ah, const bf16* __restrict__ Al,
             const bf16* __restrict__ Bh, const bf16* __restrict__ Bl,
             const float* __restrict__ bias,
             bf16* __restrict__ Ch, bf16* __restrict__ Cl,
             __half* __restrict__ Hx, float* __restrict__ Fx,
             int Ktot, int Nsplit, int Nld, int relu)
{
    extern __shared__ char smem[];
    unsigned sbase = smem_u32(smem);
    int tid = threadIdx.x;
    int lane = tid & 31, wrp = tid >> 5;
    int wm = wrp & 1, wn = wrp >> 1;
    int row0 = blockIdx.y * 64, col0 = blockIdx.x * 128;

    float c[2][4][4];
#pragma unroll
    for (int i = 0; i < 2; i++)
#pragma unroll
        for (int j = 0; j < 4; j++)
#pragma unroll
            for (int q = 0; q < 4; q++) c[i][j][q] = 0.f;

    int nk = Ktot >> 6;
    stage_load(sbase, 0, Ah, Al, Bh, Bl, row0, col0, 0, Ktot, tid);
    CP_COMMIT();

    for (int it = 0; it < nk; it++) {
        if (it + 1 < nk) {
            stage_load(sbase, (it + 1) & 1, Ah, Al, Bh, Bl, row0, col0,
                       (it + 1) << 6, Ktot, tid);
            CP_COMMIT();
            CP_WAIT1();
        } else {
            CP_WAIT0();
        }
        __syncthreads();

        unsigned stb = sbase + (unsigned)((it & 1) * STG_B);

#pragma unroll
        for (int ks = 0; ks < 4; ks++) {
            int kc = ks * 16;
            unsigned ah[2][4], al[2][4], bh[2][4], bl[2][4];
#pragma unroll
            for (int ma = 0; ma < 2; ma++) {
                int el = (wm * 32 + ma * 16 + (lane & 15)) * PADK
                       + kc + ((lane >> 4) << 3);
                LDSM4(ah[ma], stb + OFF_AH + el * 2);
                LDSM4(al[ma], stb + OFF_AL + el * 2);
            }
#pragma unroll
            for (int nb = 0; nb < 2; nb++) {
                int n = wn * 32 + nb * 16 + ((lane >> 4) << 3) + (lane & 7);
                int el = n * PADK + kc + (((lane >> 3) & 1) << 3);
                LDSM4(bh[nb], stb + OFF_BH + el * 2);
                LDSM4(bl[nb], stb + OFF_BL + el * 2);
            }
#pragma unroll
            for (int ma = 0; ma < 2; ma++)
#pragma unroll
                for (int na = 0; na < 4; na++) {
                    const unsigned* bph = &bh[na >> 1][(na & 1) * 2];
                    const unsigned* bpl = &bl[na >> 1][(na & 1) * 2];
                    MMA16816(c[ma][na], ah[ma], bph);
                    MMA16816(c[ma][na], ah[ma], bpl);
                    MMA16816(c[ma][na], al[ma], bph);
                }
        }
        __syncthreads();
    }

#pragma unroll
    for (int ma = 0; ma < 2; ma++) {
        int r0 = row0 + wm * 32 + ma * 16 + (lane >> 2);
#pragma unroll
        for (int na = 0; na < 4; na++) {
            int col = col0 + wn * 32 + na * 8 + ((lane & 3) << 1);
            emit2(r0,     col, make_float2(c[ma][na][0], c[ma][na][1]),
                  bias, relu, Ch, Cl, Hx, Fx, Nsplit, Nld);
            emit2(r0 + 8, col, make_float2(c[ma][na][2], c[ma][na][3]),
                  bias, relu, Ch, Cl, Hx, Fx, Nsplit, Nld);
        }
    }
}

/* ------------------ GATv2 aggregation helpers ---------------------------- */
__device__ __forceinline__ float lrelu(float x) { return x > 0.f ? x : NEG * x; }

struct OSM { float m, s; float4 acc; };
__device__ __forceinline__ void osm_init(OSM& o) {
    o.m = -1e30f; o.s = 0.f; o.acc = make_float4(0.f, 0.f, 0.f, 0.f);
}
__device__ __forceinline__ void osm_step(OSM& o, float4 l4, float4 r4, float4 a4) {
    float p = lrelu(l4.x + r4.x) * a4.x;
    p      += lrelu(l4.y + r4.y) * a4.y;
    p      += lrelu(l4.z + r4.z) * a4.z;
    p      += lrelu(l4.w + r4.w) * a4.w;
#pragma unroll
    for (int off = 16; off > 0; off >>= 1) p += __shfl_xor_sync(0xffffffffu, p, off);
    float mn = fmaxf(o.m, p);
    float cc = __expf(o.m - mn);
    float wg = __expf(p - mn);
    o.s = o.s * cc + wg;
    o.acc.x = o.acc.x * cc + wg * l4.x;
    o.acc.y = o.acc.y * cc + wg * l4.y;
    o.acc.z = o.acc.z * cc + wg * l4.z;
    o.acc.w = o.acc.w * cc + wg * l4.w;
    o.m = mn;
}
__device__ __forceinline__ void osm_merge(OSM& a, const OSM& b) {
    float mn = fmaxf(a.m, b.m);
    float ca = __expf(a.m - mn), cb = __expf(b.m - mn);
    a.s = a.s * ca + b.s * cb;
    a.acc.x = a.acc.x * ca + b.acc.x * cb;
    a.acc.y = a.acc.y * ca + b.acc.y * cb;
    a.acc.z = a.acc.z * ca + b.acc.z * cb;
    a.acc.w = a.acc.w * ca + b.acc.w * cb;
    a.m = mn;
}

/* ------------------ layer-1 aggregation (fp16 xl) ------------------------ */
__global__ void gat_agg1(const __half* __restrict__ xl, const float* __restrict__ xr,
                         const float* __restrict__ att, const float* __restrict__ bias,
                         bf16* __restrict__ oh, bf16* __restrict__ ol)
{
    const int HEADS = 4, D = 512;
    int w = (blockIdx.x * blockDim.x + threadIdx.x) >> 5;
    int lane = threadIdx.x & 31;
    if (w >= N_NODES * HEADS) return;
    int dst = w / HEADS;
    int h   = w - dst * HEADS;
    int cb = h * HID + lane * 4;

    float4 a4 = *(const float4*)(att + h * HID + lane * 4);
    float4 r4 = *(const float4*)(xr + (size_t)dst * D + cb);

    OSM o0, o1;
    osm_init(o0); osm_init(o1);

    int j = g_off[dst], end = g_off[dst + 1];
    if ((end - j) & 1) {
        float4 l4 = ldh4(xl + (size_t)g_srcs[j] * D + cb);
        osm_step(o0, l4, r4, a4);
        j++;
    }
    for (; j < end; j += 2) {
        int sA = g_srcs[j], sB = g_srcs[j + 1];
        float4 lA = ldh4(xl + (size_t)sA * D + cb);
        float4 lB = ldh4(xl + (size_t)sB * D + cb);
        osm_step(o0, lA, r4, a4);
        osm_step(o1, lB, r4, a4);
    }
    osm_merge(o0, o1);

    float inv = 1.f / (o0.s + 1e-16f);
    float4 bb = *(const float4*)(bias + h * HID + lane * 4);
    float4 o4;
    o4.x = fmaxf(o0.acc.x * inv + bb.x, 0.f);
    o4.y = fmaxf(o0.acc.y * inv + bb.y, 0.f);
    o4.z = fmaxf(o0.acc.z * inv + bb.z, 0.f);
    o4.w = fmaxf(o0.acc.w * inv + bb.w, 0.f);
    split_store4(oh, ol, (size_t)dst * 512 + cb, o4);
}

/* -------- layer-2 aggregation (fp16 xl) fused with output projection ---- */
__global__ void gat_out(const __half* __restrict__ xl, const float* __restrict__ xr,
                        const float* __restrict__ att, const float* __restrict__ bias,
                        const float* __restrict__ W, const float* __restrict__ ob,
                        float* __restrict__ y)
{
    const int D = 128;
    __shared__ float Ws[HID * 10];
    __shared__ float bs[10];
    for (int i = threadIdx.x; i < HID * 10; i += blockDim.x) Ws[i] = W[i];
    if (threadIdx.x < 10) bs[threadIdx.x] = ob[threadIdx.x];
    __syncthreads();

    int w = (blockIdx.x * blockDim.x + threadIdx.x) >> 5;
    int lane = threadIdx.x & 31;
    if (w >= N_NODES) return;
    int dst = w;
    int cb = lane * 4;

    float4 a4 = *(const float4*)(att + cb);
    float4 r4 = *(const float4*)(xr + (size_t)dst * D + cb);

    OSM o0, o1;
    osm_init(o0); osm_init(o1);

    int j = g_off[dst], end = g_off[dst + 1];
    if ((end - j) & 1) {
        float4 l4 = ldh4(xl + (size_t)g_srcs[j] * D + cb);
        osm_step(o0, l4, r4, a4);
        j++;
    }
    for (; j < end; j += 2) {
        int sA = g_srcs[j], sB = g_srcs[j + 1];
        float4 lA = ldh4(xl + (size_t)sA * D + cb);
        float4 lB = ldh4(xl + (size_t)sB * D + cb);
        osm_step(o0, lA, r4, a4);
        osm_step(o1, lB, r4, a4);
    }
    osm_merge(o0, o1);

    float inv = 1.f / (o0.s + 1e-16f);
    float4 bb = *(const float4*)(bias + cb);
    float4 o4;
    o4.x = o0.acc.x * inv + bb.x;
    o4.y = o0.acc.y * inv + bb.y;
    o4.z = o0.acc.z * inv + bb.z;
    o4.w = o0.acc.w * inv + bb.w;

    /* fused [128] @ [128,10] */
    int k = lane * 4;
    float p[10];
#pragma unroll
    for (int o = 0; o < 10; o++)
        p[o] = o4.x * Ws[(k + 0) * 10 + o] + o4.y * Ws[(k + 1) * 10 + o] +
               o4.z * Ws[(k + 2) * 10 + o] + o4.w * Ws[(k + 3) * 10 + o];
#pragma unroll
    for (int o = 0; o < 10; o++)
#pragma unroll
        for (int off = 16; off > 0; off >>= 1)
            p[o] += __shfl_xor_sync(0xffffffffu, p[o], off);
    if (lane < 10) y[(size_t)dst * 10 + lane] = p[lane] + bs[lane];
}

/* ------------------ launch ---------------------------------------------- */
extern "C" void kernel_launch(void* const* d_in, const int* in_sizes, int n_in,
                              void* d_out, int out_size)
{
    const float* x_player   = (const float*)d_in[0];
    const int*   edge_index = (const int*)  d_in[1];
    const float* emb        = (const float*)d_in[2];
    const float* proj_W     = (const float*)d_in[3];
    const float* proj_b     = (const float*)d_in[4];
    const float* W1l        = (const float*)d_in[5];
    const float* W1r        = (const float*)d_in[6];
    const float* att1       = (const float*)d_in[7];
    const float* b1         = (const float*)d_in[8];
    const float* W2l        = (const float*)d_in[9];
    const float* W2r        = (const float*)d_in[10];
    const float* att2       = (const float*)d_in[11];
    const float* b2         = (const float*)d_in[12];
    const float* out_W      = (const float*)d_in[13];
    const float* out_b      = (const float*)d_in[14];
    float* y = (float*)d_out;

    bf16 *xinh, *xinl, *x0h, *x0l, *x1h, *x1l;
    bf16 *pWh, *pWl, *W1h, *W1lo, *W2h, *W2lo;
    __half *xl1h, *xl2h;
    float *xr1f, *xr2f;
    cudaGetSymbolAddress((void**)&xinh, g_xinh); cudaGetSymbolAddress((void**)&xinl, g_xinl);
    cudaGetSymbolAddress((void**)&x0h,  g_x0h);  cudaGetSymbolAddress((void**)&x0l,  g_x0l);
    cudaGetSymbolAddress((void**)&x1h,  g_x1h);  cudaGetSymbolAddress((void**)&x1l,  g_x1l);
    cudaGetSymbolAddress((void**)&xl1h, g_xl1h); cudaGetSymbolAddress((void**)&xr1f, g_xr1f);
    cudaGetSymbolAddress((void**)&xl2h, g_xl2h); cudaGetSymbolAddress((void**)&xr2f, g_xr2f);
    cudaGetSymbolAddress((void**)&pWh,  g_pWh);  cudaGetSymbolAddress((void**)&pWl,  g_pWl);
    cudaGetSymbolAddress((void**)&W1h,  g_W1h);  cudaGetSymbolAddress((void**)&W1lo, g_W1l);
    cudaGetSymbolAddress((void**)&W2h,  g_W2h);  cudaGetSymbolAddress((void**)&W2lo, g_W2l);

    cudaFuncSetAttribute(mm_bf16, cudaFuncAttributeMaxDynamicSharedMemorySize, SM_SZ);

    /* prep (edge count + gather + weight conversion), then CSR scan+scatter */
    k_prep<<<(PREP_TOT + 255) / 256, 256>>>(edge_index, x_player, emb, proj_W,
                                            W1l, W1r, W2l, W2r);
    k_scan   <<<1, 1024>>>();
    k_scatter<<<(N_EDGES + 255) / 256, 256>>>(edge_index);

    /* proj: [MPAD,192]@[192,128] + b, relu, split-bf16 output */
    mm_bf16<<<dim3(1, MPAD / 64), 256, SM_SZ>>>(
        xinh, xinl, pWh, pWl, proj_b, x0h, x0l, nullptr, nullptr, KIN, 0, HID, 1);

    /* GAT layer 1 linear: merged GEMM N=1024 -> xl fp16 | xr fp32 */
    mm_bf16<<<dim3(8, MPAD / 64), 256, SM_SZ>>>(
        x0h, x0l, W1h, W1lo, nullptr, nullptr, nullptr, xl1h, xr1f, HID, 512, 1024, 0);
    gat_agg1<<<(N_NODES * 4 * 32 + 255) / 256, 256>>>(xl1h, xr1f, att1, b1, x1h, x1l);

    /* GAT layer 2 linear: merged GEMM N=256 -> xl fp16 | xr fp32 */
    mm_bf16<<<dim3(2, MPAD / 64), 256, SM_SZ>>>(
        x1h, x1l, W2h, W2lo, nullptr, nullptr, nullptr, xl2h, xr2f, 512, 128, 256, 0);

    /* layer-2 aggregation fused with output projection */
    gat_out<<<(N_NODES * 32 + 255) / 256, 256>>>(xl2h, xr2f, att2, b2, out_W, out_b, y);
}